// round 1
// baseline (speedup 1.0000x reference)
#include <cuda_runtime.h>
#include <cuda_bf16.h>
#include <math.h>

// ---------------------------------------------------------------------------
// Problem constants
// ---------------------------------------------------------------------------
#define DIM   384
#define NH    12
#define HD    32
#define WS    14
#define BATCH 16
#define HH    56
#define WW    56
#define NWIN  256            // BATCH * 4 * 4
#define NTOK  196            // WS*WS
#define TOK   50176          // BATCH*HH*WW = NWIN*NTOK

// ---------------------------------------------------------------------------
// Scratch (static __device__ arrays: allocation-free)
// ---------------------------------------------------------------------------
__device__ float g_X0 [(size_t)TOK * DIM];        // conv-PE output / final (reused)
__device__ float g_Y  [(size_t)TOK * DIM];        // LN output (reused for LN1, LN2)
__device__ float g_QKV[(size_t)TOK * 3 * DIM];    // qkv
__device__ float g_ATT[(size_t)TOK * DIM];        // attention output
__device__ float g_X1 [(size_t)TOK * DIM];        // after proj residual

__device__ float g_F  [(size_t)TOK * 4 * DIM];    // fc1/gelu output

// ---------------------------------------------------------------------------
// 1) depthwise 3x3 conv positional embedding, residual, write windowed BHWC
//    grid (DIM/8, HH, BATCH), block (8, 56)
// ---------------------------------------------------------------------------
__global__ void conv_pe_kernel(const float* __restrict__ x,
                               const float* __restrict__ cw,
                               const float* __restrict__ cb,
                               float* __restrict__ X0)
{
    const int cg = blockIdx.x * 8;
    const int h  = blockIdx.y;
    const int b  = blockIdx.z;

    __shared__ float sm[8][3][58];

    const int tid = threadIdx.y * 8 + threadIdx.x;   // 0..447
    const int lc  = tid / 56;                        // 0..7 (channel for load)
    const int lw  = tid % 56;                        // 0..55 (w for load, coalesced)

    const float* xp = x + ((size_t)(b * DIM + cg + lc) * HH) * WW;
#pragma unroll
    for (int r = 0; r < 3; r++) {
        int hh = h - 1 + r;
        float v = (hh >= 0 && hh < HH) ? xp[hh * WW + lw] : 0.0f;
        sm[lc][r][lw + 1] = v;
        if (lw == 0)  sm[lc][r][0]  = 0.0f;
        if (lw == 55) sm[lc][r][57] = 0.0f;
    }
    __syncthreads();

    const int c = threadIdx.x;      // 0..7 local channel
    const int w = threadIdx.y;      // 0..55

    float wreg[9];
    const float* cwp = cw + (size_t)(cg + c) * 9;
#pragma unroll
    for (int i = 0; i < 9; i++) wreg[i] = cwp[i];

    float pe = 0.0f;
#pragma unroll
    for (int kh = 0; kh < 3; kh++)
#pragma unroll
        for (int kw = 0; kw < 3; kw++)
            pe += wreg[kh * 3 + kw] * sm[c][kh][w + kw];

    float val = sm[c][1][w + 1] + pe + cb[cg + c];

    const int wi = (b * 4 + h / WS) * 4 + (w / WS);
    const int n  = (h % WS) * WS + (w % WS);
    X0[((size_t)wi * NTOK + n) * DIM + cg + c] = val;
}

// ---------------------------------------------------------------------------
// 2) LayerNorm over C=384: one warp per token, 12 elems per lane
//    grid (TOK/8), block (256)
// ---------------------------------------------------------------------------
__global__ void ln_kernel(const float* __restrict__ X,
                          const float* __restrict__ gamma,
                          const float* __restrict__ beta,
                          float* __restrict__ Y)
{
    const int warp = (blockIdx.x * blockDim.x + threadIdx.x) >> 5;
    const int lane = threadIdx.x & 31;
    if (warp >= TOK) return;

    const float* xp = X + (size_t)warp * DIM;
    float v[12];
    float s = 0.0f;
#pragma unroll
    for (int k = 0; k < 12; k++) { v[k] = xp[lane + 32 * k]; s += v[k]; }
#pragma unroll
    for (int o = 16; o; o >>= 1) s += __shfl_xor_sync(0xffffffffu, s, o);
    const float mean = s * (1.0f / DIM);

    float q = 0.0f;
#pragma unroll
    for (int k = 0; k < 12; k++) { float d = v[k] - mean; q += d * d; }
#pragma unroll
    for (int o = 16; o; o >>= 1) q += __shfl_xor_sync(0xffffffffu, q, o);
    const float inv = rsqrtf(q * (1.0f / DIM) + 1e-5f);

    float* yp = Y + (size_t)warp * DIM;
#pragma unroll
    for (int k = 0; k < 12; k++) {
        int c = lane + 32 * k;
        yp[c] = (v[k] - mean) * inv * gamma[c] + beta[c];
    }
}

// ---------------------------------------------------------------------------
// 3) Generic SGEMM: C[M,N] = act(A[M,K] @ W[N,K]^T + bias) (+ R)
//    128x128 block tile, K-tile 8, 256 threads, 8x8 per thread.
//    act: 0 = none, 1 = exact GELU (applied before residual add; fc1 has no R)
// ---------------------------------------------------------------------------
#define BM 128
#define BN 128
#define BKK 8

__global__ __launch_bounds__(256, 2)
void gemm_kernel(const float* __restrict__ A,
                 const float* __restrict__ W,
                 const float* __restrict__ bias,
                 const float* __restrict__ R,
                 float* __restrict__ C,
                 int M, int N, int K, int act)
{
    __shared__ float As[BKK][BM];
    __shared__ float Ws[BKK][BN];

    const int bm = blockIdx.y * BM;
    const int bn = blockIdx.x * BN;
    const int tid = threadIdx.x;
    const int tx = tid & 15;       // 0..15 (N dir)
    const int ty = tid >> 4;       // 0..15 (M dir)

    const int lr = tid >> 1;           // 0..127
    const int lk = (tid & 1) * 4;      // 0 or 4

    float acc[8][8];
#pragma unroll
    for (int i = 0; i < 8; i++)
#pragma unroll
        for (int j = 0; j < 8; j++) acc[i][j] = 0.0f;

    const float* Ag = A + (size_t)(bm + lr) * K + lk;
    const float* Wg = W + (size_t)(bn + lr) * K + lk;

    for (int k0 = 0; k0 < K; k0 += BKK) {
        float4 av = *(const float4*)(Ag + k0);
        float4 wv = *(const float4*)(Wg + k0);
        As[lk + 0][lr] = av.x; As[lk + 1][lr] = av.y;
        As[lk + 2][lr] = av.z; As[lk + 3][lr] = av.w;
        Ws[lk + 0][lr] = wv.x; Ws[lk + 1][lr] = wv.y;
        Ws[lk + 2][lr] = wv.z; Ws[lk + 3][lr] = wv.w;
        __syncthreads();

#pragma unroll
        for (int k = 0; k < BKK; k++) {
            float a[8], b[8];
            *(float4*)(a)     = *(const float4*)&As[k][ty * 8];
            *(float4*)(a + 4) = *(const float4*)&As[k][ty * 8 + 4];
            *(float4*)(b)     = *(const float4*)&Ws[k][tx * 8];
            *(float4*)(b + 4) = *(const float4*)&Ws[k][tx * 8 + 4];
#pragma unroll
            for (int i = 0; i < 8; i++)
#pragma unroll
                for (int j = 0; j < 8; j++)
                    acc[i][j] += a[i] * b[j];
        }
        __syncthreads();
    }

#pragma unroll
    for (int i = 0; i < 8; i++) {
        const size_t m = (size_t)(bm + ty * 8 + i);
#pragma unroll
        for (int j = 0; j < 8; j += 4) {
            const int n = bn + tx * 8 + j;
            float4 o;
            o.x = acc[i][j + 0] + bias[n + 0];
            o.y = acc[i][j + 1] + bias[n + 1];
            o.z = acc[i][j + 2] + bias[n + 2];
            o.w = acc[i][j + 3] + bias[n + 3];
            if (act == 1) {
                o.x = 0.5f * o.x * (1.0f + erff(o.x * 0.70710678118654752f));
                o.y = 0.5f * o.y * (1.0f + erff(o.y * 0.70710678118654752f));
                o.z = 0.5f * o.z * (1.0f + erff(o.z * 0.70710678118654752f));
                o.w = 0.5f * o.w * (1.0f + erff(o.w * 0.70710678118654752f));
            }
            if (R) {
                float4 r = *(const float4*)(R + m * N + n);
                o.x += r.x; o.y += r.y; o.z += r.z; o.w += r.w;
            }
            *(float4*)(C + m * N + n) = o;
        }
    }
}

// ---------------------------------------------------------------------------
// 4) Window attention: one CTA per (window, head). Q/K/V resident in smem.
//    block 256 (8 warps), each warp processes 2 rows at a time.
// ---------------------------------------------------------------------------
__global__ void attn_kernel(const float* __restrict__ QKV,
                            float* __restrict__ ATT)
{
    const int wi  = blockIdx.x / NH;
    const int hdi = blockIdx.x % NH;

    extern __shared__ float sh[];
    float* qs = sh;                        // 196*32
    float* ks = sh + NTOK * 32;            // 196*33 (padded)
    float* vs = ks + NTOK * 33;            // 196*33 (padded)

    const float* base = QKV + (size_t)wi * NTOK * (3 * DIM) + hdi * HD;
    const int tid = threadIdx.x;

    for (int idx = tid; idx < NTOK * 32; idx += 256) {
        int n = idx >> 5, d = idx & 31;
        const float* src = base + (size_t)n * (3 * DIM);
        qs[n * 32 + d] = src[d];
        ks[n * 33 + d] = src[DIM + d];
        vs[n * 33 + d] = src[2 * DIM + d];
    }
    __syncthreads();

    const int warp = tid >> 5;
    const int lane = tid & 31;
    const float scale = 0.1767766952966369f;   // 1/sqrt(32)

    for (int ii = warp * 2; ii < NTOK; ii += 16) {
        const int i0 = ii, i1 = ii + 1;

        float q0[32], q1[32];
#pragma unroll
        for (int d = 0; d < 32; d++) {
            q0[d] = qs[i0 * 32 + d];
            q1[d] = qs[i1 * 32 + d];
        }

        float s0[7], s1[7];
#pragma unroll
        for (int j = 0; j < 7; j++) {
            int m = lane + 32 * j;
            if (m < NTOK) {
                const float* kr = ks + m * 33;
                float a0 = 0.0f, a1 = 0.0f;
#pragma unroll
                for (int d = 0; d < 32; d++) {
                    float kv = kr[d];
                    a0 += q0[d] * kv;
                    a1 += q1[d] * kv;
                }
                s0[j] = a0 * scale;
                s1[j] = a1 * scale;
            } else {
                s0[j] = -1e30f;
                s1[j] = -1e30f;
            }
        }

        float mx0 = s0[0], mx1 = s1[0];
#pragma unroll
        for (int j = 1; j < 7; j++) { mx0 = fmaxf(mx0, s0[j]); mx1 = fmaxf(mx1, s1[j]); }
#pragma unroll
        for (int o = 16; o; o >>= 1) {
            mx0 = fmaxf(mx0, __shfl_xor_sync(0xffffffffu, mx0, o));
            mx1 = fmaxf(mx1, __shfl_xor_sync(0xffffffffu, mx1, o));
        }

        float p0[7], p1[7], sum0 = 0.0f, sum1 = 0.0f;
#pragma unroll
        for (int j = 0; j < 7; j++) {
            int m = lane + 32 * j;
            p0[j] = (m < NTOK) ? expf(s0[j] - mx0) : 0.0f;
            p1[j] = (m < NTOK) ? expf(s1[j] - mx1) : 0.0f;
            sum0 += p0[j];
            sum1 += p1[j];
        }
#pragma unroll
        for (int o = 16; o; o >>= 1) {
            sum0 += __shfl_xor_sync(0xffffffffu, sum0, o);
            sum1 += __shfl_xor_sync(0xffffffffu, sum1, o);
        }

        float o0 = 0.0f, o1 = 0.0f;
#pragma unroll
        for (int j = 0; j < 7; j++) {
            for (int l = 0; l < 32; l++) {
                int m = 32 * j + l;
                if (m >= NTOK) break;
                float pm0 = __shfl_sync(0xffffffffu, p0[j], l);
                float pm1 = __shfl_sync(0xffffffffu, p1[j], l);
                float vv = vs[m * 33 + lane];
                o0 += pm0 * vv;
                o1 += pm1 * vv;
            }
        }
        o0 /= sum0;
        o1 /= sum1;

        ATT[((size_t)wi * NTOK + i0) * DIM + hdi * HD + lane] = o0;
        ATT[((size_t)wi * NTOK + i1) * DIM + hdi * HD + lane] = o1;
    }
}

// ---------------------------------------------------------------------------
// 5) Windowed (wi,n,c) -> BCHW output, smem-transposed
//    grid (24, 56, 16): blockIdx.x = ct*2 + wt; block (32,8)
// ---------------------------------------------------------------------------
__global__ void unwin_kernel(const float* __restrict__ X,
                             float* __restrict__ out)
{
    const int ct = blockIdx.x >> 1, wt = blockIdx.x & 1;
    const int h = blockIdx.y, b = blockIdx.z;
    const int c0 = ct * 32, w0 = wt * 32;

    __shared__ float sm[32][33];
    const int tx = threadIdx.x, ty = threadIdx.y;

#pragma unroll
    for (int k = 0; k < 4; k++) {
        int row = ty + 8 * k;
        int w = w0 + row;
        if (w < WW) {
            int wi = (b * 4 + h / WS) * 4 + w / WS;
            int n  = (h % WS) * WS + (w % WS);
            sm[row][tx] = X[((size_t)wi * NTOK + n) * DIM + c0 + tx];
        }
    }
    __syncthreads();

#pragma unroll
    for (int k = 0; k < 4; k++) {
        int c = c0 + ty + 8 * k;
        int w = w0 + tx;
        if (w < WW)
            out[(((size_t)b * DIM + c) * HH + h) * WW + w] = sm[tx][ty + 8 * k];
    }
}

// ---------------------------------------------------------------------------
// Launch
// ---------------------------------------------------------------------------
extern "C" void kernel_launch(void* const* d_in, const int* in_sizes, int n_in,
                              void* d_out, int out_size)
{
    const float* x      = (const float*)d_in[0];
    const float* conv_w = (const float*)d_in[1];
    const float* conv_b = (const float*)d_in[2];
    const float* ln1_g  = (const float*)d_in[3];
    const float* ln1_b  = (const float*)d_in[4];
    const float* qkv_w  = (const float*)d_in[5];
    const float* qkv_b  = (const float*)d_in[6];
    const float* proj_w = (const float*)d_in[7];
    const float* proj_b = (const float*)d_in[8];
    const float* ln2_g  = (const float*)d_in[9];
    const float* ln2_b  = (const float*)d_in[10];
    const float* fc1_w  = (const float*)d_in[11];
    const float* fc1_b  = (const float*)d_in[12];
    const float* fc2_w  = (const float*)d_in[13];
    const float* fc2_b  = (const float*)d_in[14];
    float* out = (float*)d_out;

    float *X0, *Y, *QKV, *ATT, *X1, *F;
    cudaGetSymbolAddress((void**)&X0,  g_X0);
    cudaGetSymbolAddress((void**)&Y,   g_Y);
    cudaGetSymbolAddress((void**)&QKV, g_QKV);
    cudaGetSymbolAddress((void**)&ATT, g_ATT);
    cudaGetSymbolAddress((void**)&X1,  g_X1);
    cudaGetSymbolAddress((void**)&F,   g_F);

    const int attn_smem = (NTOK * 32 + 2 * NTOK * 33) * (int)sizeof(float); // 76832
    cudaFuncSetAttribute(attn_kernel, cudaFuncAttributeMaxDynamicSharedMemorySize, attn_smem);

    // 1) conv PE + residual -> X0 (windowed token order)
    conv_pe_kernel<<<dim3(DIM / 8, HH, BATCH), dim3(8, 56)>>>(x, conv_w, conv_b, X0);

    // 2) LN1 -> Y
    ln_kernel<<<TOK / 8, 256>>>(X0, ln1_g, ln1_b, Y);

    // 3) QKV GEMM: [TOK,384] x [1152,384]^T -> QKV
    gemm_kernel<<<dim3(3 * DIM / BN, TOK / BM), 256>>>(Y, qkv_w, qkv_b, nullptr, QKV,
                                                       TOK, 3 * DIM, DIM, 0);

    // 4) window attention -> ATT
    attn_kernel<<<NWIN * NH, 256, attn_smem>>>(QKV, ATT);

    // 5) proj GEMM + residual(X0) -> X1
    gemm_kernel<<<dim3(DIM / BN, TOK / BM), 256>>>(ATT, proj_w, proj_b, X0, X1,
                                                   TOK, DIM, DIM, 0);

    // 6) LN2 -> Y
    ln_kernel<<<TOK / 8, 256>>>(X1, ln2_g, ln2_b, Y);

    // 7) FC1 GEMM + GELU -> F
    gemm_kernel<<<dim3(4 * DIM / BN, TOK / BM), 256>>>(Y, fc1_w, fc1_b, nullptr, F,
                                                       TOK, 4 * DIM, DIM, 1);

    // 8) FC2 GEMM + residual(X1) -> X0 (reuse)
    gemm_kernel<<<dim3(DIM / BN, TOK / BM), 256>>>(F, fc2_w, fc2_b, X1, X0,
                                                   TOK, DIM, 4 * DIM, 0);

    // 9) un-window + transpose to BCHW -> out
    unwin_kernel<<<dim3(24, HH, BATCH), dim3(32, 8)>>>(X0, out);
}

// round 3
// speedup vs baseline: 2.2281x; 2.2281x over previous
#include <cuda_runtime.h>
#include <cuda_bf16.h>
#include <math.h>
#include <cstdint>

// ---------------------------------------------------------------------------
// Problem constants
// ---------------------------------------------------------------------------
#define DIM   384
#define NH    12
#define HD    32
#define WS    14
#define BATCH 16
#define HH    56
#define WW    56
#define NWIN  256
#define NTOK  196
#define TOK   50176          // NWIN*NTOK, = 196*256

// ---------------------------------------------------------------------------
// Scratch
// ---------------------------------------------------------------------------
__device__ float g_X0 [(size_t)TOK * DIM];
__device__ float g_Y  [(size_t)TOK * DIM];
__device__ float g_QKV[(size_t)TOK * 3 * DIM];
__device__ float g_ATT[(size_t)TOK * DIM];
__device__ float g_X1 [(size_t)TOK * DIM];
__device__ float g_F  [(size_t)TOK * 4 * DIM];
__device__ float g_Wc [1769472];                 // tf32-rounded weights

#define WOFF_QKV  0
#define WOFF_PROJ (3 * DIM * DIM)                       // 442368
#define WOFF_FC1  (WOFF_PROJ + DIM * DIM)               // 589824
#define WOFF_FC2  (WOFF_FC1 + 4 * DIM * DIM)            // 1179648

// ---------------------------------------------------------------------------
// helpers
// ---------------------------------------------------------------------------
__device__ __forceinline__ float tf32_rna(float x) {
    uint32_t u;
    asm("cvt.rna.tf32.f32 %0, %1;" : "=r"(u) : "f"(x));
    return __uint_as_float(u);
}
__device__ __forceinline__ uint32_t smem_u32(const void* p) {
    uint32_t a;
    asm("{ .reg .u64 t; cvta.to.shared.u64 t, %1; cvt.u32.u64 %0, t; }" : "=r"(a) : "l"(p));
    return a;
}
__device__ __forceinline__ void cp16(uint32_t dst, const float* src) {
    asm volatile("cp.async.cg.shared.global [%0], [%1], 16;" :: "r"(dst), "l"(src));
}
#define CP_COMMIT() asm volatile("cp.async.commit_group;" ::: "memory")
#define CP_WAIT1()  asm volatile("cp.async.wait_group 1;" ::: "memory")

__device__ __forceinline__ void mma_tf32(float* d, const float* a, const float* b) {
    uint32_t const* A = reinterpret_cast<uint32_t const*>(a);
    uint32_t const* B = reinterpret_cast<uint32_t const*>(b);
    asm volatile(
        "mma.sync.aligned.m16n8k8.row.col.f32.tf32.tf32.f32 "
        "{%0,%1,%2,%3}, {%4,%5,%6,%7}, {%8,%9}, {%0,%1,%2,%3};"
        : "+f"(d[0]), "+f"(d[1]), "+f"(d[2]), "+f"(d[3])
        : "r"(A[0]), "r"(A[1]), "r"(A[2]), "r"(A[3]), "r"(B[0]), "r"(B[1]));
}

// ---------------------------------------------------------------------------
// 0) weight conversion to tf32 (rna)
// ---------------------------------------------------------------------------
__global__ void cvtw_kernel(const float* __restrict__ src, float* __restrict__ dst, int n)
{
    int i = blockIdx.x * blockDim.x + threadIdx.x;
    if (i < n) dst[i] = tf32_rna(src[i]);
}

// ---------------------------------------------------------------------------
// 1) depthwise 3x3 conv PE + residual -> windowed (wi,n,c)
// ---------------------------------------------------------------------------
__global__ void conv_pe_kernel(const float* __restrict__ x,
                               const float* __restrict__ cw,
                               const float* __restrict__ cb,
                               float* __restrict__ X0)
{
    const int cg = blockIdx.x * 8;
    const int h  = blockIdx.y;
    const int b  = blockIdx.z;

    __shared__ float sm[8][3][58];

    const int tid = threadIdx.y * 8 + threadIdx.x;
    const int lc  = tid / 56;
    const int lw  = tid % 56;

    const float* xp = x + ((size_t)(b * DIM + cg + lc) * HH) * WW;
#pragma unroll
    for (int r = 0; r < 3; r++) {
        int hh = h - 1 + r;
        float v = (hh >= 0 && hh < HH) ? xp[hh * WW + lw] : 0.0f;
        sm[lc][r][lw + 1] = v;
        if (lw == 0)  sm[lc][r][0]  = 0.0f;
        if (lw == 55) sm[lc][r][57] = 0.0f;
    }
    __syncthreads();

    const int c = threadIdx.x;
    const int w = threadIdx.y;

    float wreg[9];
    const float* cwp = cw + (size_t)(cg + c) * 9;
#pragma unroll
    for (int i = 0; i < 9; i++) wreg[i] = cwp[i];

    float pe = 0.0f;
#pragma unroll
    for (int kh = 0; kh < 3; kh++)
#pragma unroll
        for (int kw = 0; kw < 3; kw++)
            pe += wreg[kh * 3 + kw] * sm[c][kh][w + kw];

    float val = sm[c][1][w + 1] + pe + cb[cg + c];

    const int wi = (b * 4 + h / WS) * 4 + (w / WS);
    const int n  = (h % WS) * WS + (w % WS);
    X0[((size_t)wi * NTOK + n) * DIM + cg + c] = val;
}

// ---------------------------------------------------------------------------
// 2) LayerNorm; output rounded to tf32 (it's only consumed as GEMM A operand)
// ---------------------------------------------------------------------------
__global__ void ln_kernel(const float* __restrict__ X,
                          const float* __restrict__ gamma,
                          const float* __restrict__ beta,
                          float* __restrict__ Y)
{
    const int warp = (blockIdx.x * blockDim.x + threadIdx.x) >> 5;
    const int lane = threadIdx.x & 31;
    if (warp >= TOK) return;

    const float* xp = X + (size_t)warp * DIM;
    float v[12];
    float s = 0.0f;
#pragma unroll
    for (int k = 0; k < 12; k++) { v[k] = xp[lane + 32 * k]; s += v[k]; }
#pragma unroll
    for (int o = 16; o; o >>= 1) s += __shfl_xor_sync(0xffffffffu, s, o);
    const float mean = s * (1.0f / DIM);

    float q = 0.0f;
#pragma unroll
    for (int k = 0; k < 12; k++) { float d = v[k] - mean; q += d * d; }
#pragma unroll
    for (int o = 16; o; o >>= 1) q += __shfl_xor_sync(0xffffffffu, q, o);
    const float inv = rsqrtf(q * (1.0f / DIM) + 1e-5f);

    float* yp = Y + (size_t)warp * DIM;
#pragma unroll
    for (int k = 0; k < 12; k++) {
        int c = lane + 32 * k;
        yp[c] = tf32_rna((v[k] - mean) * inv * gamma[c] + beta[c]);
    }
}

// ---------------------------------------------------------------------------
// 3) TF32 mma.sync GEMM: C[M,N] = act(A[M,K] @ W[N,K]^T + bias) (+ R)
//    CTA tile 256x128, BK=32, 8 warps (4x2), warp tile 64x64, 3-stage cp.async.
//    M%256==0, N%128==0, K%32==0.  A and W must be tf32-rounded already.
// ---------------------------------------------------------------------------
#define BM 256
#define BN 128
#define BK 32
#define ASTR 36                              // smem row stride (floats)
#define A_ST_FL (BM * ASTR)                  // 9216 floats
#define B_ST_FL (BN * ASTR)                  // 4608 floats
#define STAGE_FL (A_ST_FL + B_ST_FL)         // 13824 floats = 55296 B
#define GEMM_SMEM (3 * STAGE_FL * 4)         // 165888 B

__global__ __launch_bounds__(256, 1)
void mma_gemm_kernel(const float* __restrict__ A,
                     const float* __restrict__ W,
                     const float* __restrict__ bias,
                     const float* __restrict__ R,
                     float* __restrict__ C,
                     int M, int N, int K, int act)
{
    extern __shared__ float sm[];
    const int tid  = threadIdx.x;
    const int lane = tid & 31;
    const int wid  = tid >> 5;
    const int bm = blockIdx.y * BM;
    const int bn = blockIdx.x * BN;

    const int warp_m = (wid & 3) * 64;
    const int warp_n = (wid >> 2) * 64;

    const uint32_t smem_base = smem_u32(sm);

    float acc[4][8][4];
#pragma unroll
    for (int im = 0; im < 4; im++)
#pragma unroll
        for (int in = 0; in < 8; in++)
#pragma unroll
            for (int j = 0; j < 4; j++) acc[im][in][j] = 0.0f;

    const int lr = tid >> 3;      // 0..31
    const int lc = tid & 7;       // 0..7

    const int NC = K >> 5;

    // stage fill with cp.async
    auto fill = [&](int kc, int st) {
        const int k0 = kc << 5;
        const uint32_t abase = smem_base + (uint32_t)(st * STAGE_FL) * 4;
        const uint32_t bbase = abase + A_ST_FL * 4;
        const float* Ag = A + (size_t)(bm + lr) * K + k0 + lc * 4;
        const float* Wg = W + (size_t)(bn + lr) * K + k0 + lc * 4;
#pragma unroll
        for (int i = 0; i < 8; i++)
            cp16(abase + (uint32_t)(((lr + 32 * i) * ASTR + lc * 4) * 4), Ag + (size_t)32 * i * K);
#pragma unroll
        for (int i = 0; i < 4; i++)
            cp16(bbase + (uint32_t)(((lr + 32 * i) * ASTR + lc * 4) * 4), Wg + (size_t)32 * i * K);
    };

    fill(0, 0); CP_COMMIT();
    fill(1, 1); CP_COMMIT();

    for (int kc = 0; kc < NC; kc++) {
        CP_WAIT1();
        __syncthreads();

        const int st = kc % 3;
        const float* As = sm + st * STAGE_FL;
        const float* Bs = As + A_ST_FL;
        const int rq = lane >> 2;
        const int kq = lane & 3;

#pragma unroll
        for (int s = 0; s < 4; s++) {
            const int k0 = s * 8 + kq;
            float a[4][4], b[8][2];
#pragma unroll
            for (int im = 0; im < 4; im++) {
                const float* ap = As + (warp_m + im * 16 + rq) * ASTR + k0;
                a[im][0] = ap[0];
                a[im][1] = ap[8 * ASTR];
                a[im][2] = ap[4];
                a[im][3] = ap[8 * ASTR + 4];
            }
#pragma unroll
            for (int in = 0; in < 8; in++) {
                const float* bp = Bs + (warp_n + in * 8 + rq) * ASTR + k0;
                b[in][0] = bp[0];
                b[in][1] = bp[4];
            }
#pragma unroll
            for (int im = 0; im < 4; im++)
#pragma unroll
                for (int in = 0; in < 8; in++)
                    mma_tf32(acc[im][in], a[im], b[in]);
        }

        __syncthreads();
        if (kc + 2 < NC) { fill(kc + 2, (kc + 2) % 3); CP_COMMIT(); }
    }

    // epilogue
    const int rq = lane >> 2;
    const int cq = (lane & 3) * 2;
#pragma unroll
    for (int im = 0; im < 4; im++) {
        const int row0 = bm + warp_m + im * 16 + rq;
#pragma unroll
        for (int in = 0; in < 8; in++) {
            const int col = bn + warp_n + in * 8 + cq;
            const float2 bv = *(const float2*)(bias + col);
            float v0 = acc[im][in][0] + bv.x;
            float v1 = acc[im][in][1] + bv.y;
            float v2 = acc[im][in][2] + bv.x;
            float v3 = acc[im][in][3] + bv.y;
            if (act == 1) {
                v0 = tf32_rna(0.5f * v0 * (1.0f + erff(v0 * 0.70710678118654752f)));
                v1 = tf32_rna(0.5f * v1 * (1.0f + erff(v1 * 0.70710678118654752f)));
                v2 = tf32_rna(0.5f * v2 * (1.0f + erff(v2 * 0.70710678118654752f)));
                v3 = tf32_rna(0.5f * v3 * (1.0f + erff(v3 * 0.70710678118654752f)));
            }
            if (R) {
                const float2 r0 = *(const float2*)(R + (size_t)row0 * N + col);
                const float2 r1 = *(const float2*)(R + (size_t)(row0 + 8) * N + col);
                v0 += r0.x; v1 += r0.y; v2 += r1.x; v3 += r1.y;
            }
            *(float2*)(C + (size_t)row0 * N + col)       = make_float2(v0, v1);
            *(float2*)(C + (size_t)(row0 + 8) * N + col) = make_float2(v2, v3);
        }
    }
}

// ---------------------------------------------------------------------------
// 4) Window attention (outputs rounded to tf32 — consumed as GEMM A operand)
// ---------------------------------------------------------------------------
__global__ void attn_kernel(const float* __restrict__ QKV,
                            float* __restrict__ ATT)
{
    const int wi  = blockIdx.x / NH;
    const int hdi = blockIdx.x % NH;

    extern __shared__ float sh[];
    float* qs = sh;
    float* ks = sh + NTOK * 32;
    float* vs = ks + NTOK * 33;

    const float* base = QKV + (size_t)wi * NTOK * (3 * DIM) + hdi * HD;
    const int tid = threadIdx.x;

    for (int idx = tid; idx < NTOK * 32; idx += 256) {
        int n = idx >> 5, d = idx & 31;
        const float* src = base + (size_t)n * (3 * DIM);
        qs[n * 32 + d] = src[d];
        ks[n * 33 + d] = src[DIM + d];
        vs[n * 33 + d] = src[2 * DIM + d];
    }
    __syncthreads();

    const int warp = tid >> 5;
    const int lane = tid & 31;
    const float scale = 0.1767766952966369f;

    for (int ii = warp * 2; ii < NTOK; ii += 16) {
        const int i0 = ii, i1 = ii + 1;

        float q0[32], q1[32];
#pragma unroll
        for (int d = 0; d < 32; d++) {
            q0[d] = qs[i0 * 32 + d];
            q1[d] = qs[i1 * 32 + d];
        }

        float s0[7], s1[7];
#pragma unroll
        for (int j = 0; j < 7; j++) {
            int m = lane + 32 * j;
            if (m < NTOK) {
                const float* kr = ks + m * 33;
                float a0 = 0.0f, a1 = 0.0f;
#pragma unroll
                for (int d = 0; d < 32; d++) {
                    float kv = kr[d];
                    a0 += q0[d] * kv;
                    a1 += q1[d] * kv;
                }
                s0[j] = a0 * scale;
                s1[j] = a1 * scale;
            } else {
                s0[j] = -1e30f;
                s1[j] = -1e30f;
            }
        }

        float mx0 = s0[0], mx1 = s1[0];
#pragma unroll
        for (int j = 1; j < 7; j++) { mx0 = fmaxf(mx0, s0[j]); mx1 = fmaxf(mx1, s1[j]); }
#pragma unroll
        for (int o = 16; o; o >>= 1) {
            mx0 = fmaxf(mx0, __shfl_xor_sync(0xffffffffu, mx0, o));
            mx1 = fmaxf(mx1, __shfl_xor_sync(0xffffffffu, mx1, o));
        }

        float p0[7], p1[7], sum0 = 0.0f, sum1 = 0.0f;
#pragma unroll
        for (int j = 0; j < 7; j++) {
            int m = lane + 32 * j;
            p0[j] = (m < NTOK) ? expf(s0[j] - mx0) : 0.0f;
            p1[j] = (m < NTOK) ? expf(s1[j] - mx1) : 0.0f;
            sum0 += p0[j];
            sum1 += p1[j];
        }
#pragma unroll
        for (int o = 16; o; o >>= 1) {
            sum0 += __shfl_xor_sync(0xffffffffu, sum0, o);
            sum1 += __shfl_xor_sync(0xffffffffu, sum1, o);
        }

        float o0 = 0.0f, o1 = 0.0f;
#pragma unroll
        for (int j = 0; j < 7; j++) {
            for (int l = 0; l < 32; l++) {
                int m = 32 * j + l;
                if (m >= NTOK) break;
                float pm0 = __shfl_sync(0xffffffffu, p0[j], l);
                float pm1 = __shfl_sync(0xffffffffu, p1[j], l);
                float vv = vs[m * 33 + lane];
                o0 += pm0 * vv;
                o1 += pm1 * vv;
            }
        }
        o0 /= sum0;
        o1 /= sum1;

        ATT[((size_t)wi * NTOK + i0) * DIM + hdi * HD + lane] = tf32_rna(o0);
        ATT[((size_t)wi * NTOK + i1) * DIM + hdi * HD + lane] = tf32_rna(o1);
    }
}

// ---------------------------------------------------------------------------
// 5) Windowed (wi,n,c) -> BCHW output
// ---------------------------------------------------------------------------
__global__ void unwin_kernel(const float* __restrict__ X,
                             float* __restrict__ out)
{
    const int ct = blockIdx.x >> 1, wt = blockIdx.x & 1;
    const int h = blockIdx.y, b = blockIdx.z;
    const int c0 = ct * 32, w0 = wt * 32;

    __shared__ float sm[32][33];
    const int tx = threadIdx.x, ty = threadIdx.y;

#pragma unroll
    for (int k = 0; k < 4; k++) {
        int r = ty + 8 * k;
        int w = w0 + r;
        if (w < WW) {
            int wi = (b * 4 + h / WS) * 4 + w / WS;
            int n  = (h % WS) * WS + (w % WS);
            sm[r][tx] = X[((size_t)wi * NTOK + n) * DIM + c0 + tx];
        }
    }
    __syncthreads();

#pragma unroll
    for (int k = 0; k < 4; k++) {
        int c = c0 + ty + 8 * k;
        int w = w0 + tx;
        if (w < WW)
            out[(((size_t)b * DIM + c) * HH + h) * WW + w] = sm[tx][ty + 8 * k];
    }
}

// ---------------------------------------------------------------------------
// Launch
// ---------------------------------------------------------------------------
extern "C" void kernel_launch(void* const* d_in, const int* in_sizes, int n_in,
                              void* d_out, int out_size)
{
    const float* x      = (const float*)d_in[0];
    const float* conv_w = (const float*)d_in[1];
    const float* conv_b = (const float*)d_in[2];
    const float* ln1_g  = (const float*)d_in[3];
    const float* ln1_b  = (const float*)d_in[4];
    const float* qkv_w  = (const float*)d_in[5];
    const float* qkv_b  = (const float*)d_in[6];
    const float* proj_w = (const float*)d_in[7];
    const float* proj_b = (const float*)d_in[8];
    const float* ln2_g  = (const float*)d_in[9];
    const float* ln2_b  = (const float*)d_in[10];
    const float* fc1_w  = (const float*)d_in[11];
    const float* fc1_b  = (const float*)d_in[12];
    const float* fc2_w  = (const float*)d_in[13];
    const float* fc2_b  = (const float*)d_in[14];
    float* out = (float*)d_out;

    float *X0, *Y, *QKV, *ATT, *X1, *F, *Wc;
    cudaGetSymbolAddress((void**)&X0,  g_X0);
    cudaGetSymbolAddress((void**)&Y,   g_Y);
    cudaGetSymbolAddress((void**)&QKV, g_QKV);
    cudaGetSymbolAddress((void**)&ATT, g_ATT);
    cudaGetSymbolAddress((void**)&X1,  g_X1);
    cudaGetSymbolAddress((void**)&F,   g_F);
    cudaGetSymbolAddress((void**)&Wc,  g_Wc);

    const int attn_smem = (NTOK * 32 + 2 * NTOK * 33) * (int)sizeof(float);
    cudaFuncSetAttribute(attn_kernel, cudaFuncAttributeMaxDynamicSharedMemorySize, attn_smem);
    cudaFuncSetAttribute(mma_gemm_kernel, cudaFuncAttributeMaxDynamicSharedMemorySize, GEMM_SMEM);

    // 0) tf32-round weights
    cvtw_kernel<<<(3 * DIM * DIM + 255) / 256, 256>>>(qkv_w,  Wc + WOFF_QKV,  3 * DIM * DIM);
    cvtw_kernel<<<(DIM * DIM + 255) / 256, 256>>>(proj_w, Wc + WOFF_PROJ, DIM * DIM);
    cvtw_kernel<<<(4 * DIM * DIM + 255) / 256, 256>>>(fc1_w,  Wc + WOFF_FC1,  4 * DIM * DIM);
    cvtw_kernel<<<(4 * DIM * DIM + 255) / 256, 256>>>(fc2_w,  Wc + WOFF_FC2,  4 * DIM * DIM);

    // 1) conv PE + residual -> X0
    conv_pe_kernel<<<dim3(DIM / 8, HH, BATCH), dim3(8, 56)>>>(x, conv_w, conv_b, X0);

    // 2) LN1 -> Y (tf32-rounded)
    ln_kernel<<<TOK / 8, 256>>>(X0, ln1_g, ln1_b, Y);

    // 3) QKV GEMM
    mma_gemm_kernel<<<dim3(3 * DIM / BN, TOK / BM), 256, GEMM_SMEM>>>(
        Y, Wc + WOFF_QKV, qkv_b, nullptr, QKV, TOK, 3 * DIM, DIM, 0);

    // 4) window attention -> ATT (tf32-rounded)
    attn_kernel<<<NWIN * NH, 256, attn_smem>>>(QKV, ATT);

    // 5) proj GEMM + residual(X0) -> X1
    mma_gemm_kernel<<<dim3(DIM / BN, TOK / BM), 256, GEMM_SMEM>>>(
        ATT, Wc + WOFF_PROJ, proj_b, X0, X1, TOK, DIM, DIM, 0);

    // 6) LN2 -> Y (tf32-rounded)
    ln_kernel<<<TOK / 8, 256>>>(X1, ln2_g, ln2_b, Y);

    // 7) FC1 GEMM + GELU -> F (tf32-rounded)
    mma_gemm_kernel<<<dim3(4 * DIM / BN, TOK / BM), 256, GEMM_SMEM>>>(
        Y, Wc + WOFF_FC1, fc1_b, nullptr, F, TOK, 4 * DIM, DIM, 1);

    // 8) FC2 GEMM + residual(X1) -> X0
    mma_gemm_kernel<<<dim3(DIM / BN, TOK / BM), 256, GEMM_SMEM>>>(
        F, Wc + WOFF_FC2, fc2_b, X1, X0, TOK, DIM, 4 * DIM, 0);

    // 9) un-window -> BCHW
    unwin_kernel<<<dim3(24, HH, BATCH), dim3(32, 8)>>>(X0, out);
}

// round 4
// speedup vs baseline: 3.1899x; 1.4317x over previous
#include <cuda_runtime.h>
#include <cuda_bf16.h>
#include <math.h>
#include <cstdint>

// ---------------------------------------------------------------------------
// Problem constants
// ---------------------------------------------------------------------------
#define DIM   384
#define NH    12
#define HD    32
#define WS    14
#define BATCH 16
#define HH    56
#define WW    56
#define NWIN  256
#define NTOK  196
#define TOK   50176          // NWIN*NTOK

// ---------------------------------------------------------------------------
// Scratch
// ---------------------------------------------------------------------------
__device__ float g_X0 [(size_t)TOK * DIM];
__device__ float g_Y  [(size_t)TOK * DIM];
__device__ float g_QKV[(size_t)TOK * 3 * DIM];
__device__ float g_ATT[(size_t)TOK * DIM];
__device__ float g_X1 [(size_t)TOK * DIM];
__device__ float g_F  [(size_t)TOK * 4 * DIM];
__device__ float g_Wc [1769472];                 // tf32-rounded weights

#define WOFF_QKV  0
#define WOFF_PROJ (3 * DIM * DIM)
#define WOFF_FC1  (WOFF_PROJ + DIM * DIM)
#define WOFF_FC2  (WOFF_FC1 + 4 * DIM * DIM)

// ---------------------------------------------------------------------------
// helpers
// ---------------------------------------------------------------------------
__device__ __forceinline__ float tf32_rna(float x) {
    uint32_t u;
    asm("cvt.rna.tf32.f32 %0, %1;" : "=r"(u) : "f"(x));
    return __uint_as_float(u);
}
__device__ __forceinline__ uint32_t smem_u32(const void* p) {
    uint32_t a;
    asm("{ .reg .u64 t; cvta.to.shared.u64 t, %1; cvt.u32.u64 %0, t; }" : "=r"(a) : "l"(p));
    return a;
}
__device__ __forceinline__ void cp16(uint32_t dst, const float* src) {
    asm volatile("cp.async.cg.shared.global [%0], [%1], 16;" :: "r"(dst), "l"(src));
}
#define CP_COMMIT() asm volatile("cp.async.commit_group;" ::: "memory")
#define CP_WAIT1()  asm volatile("cp.async.wait_group 1;" ::: "memory")

__device__ __forceinline__ void mma_tf32(float* d, const float* a, const float* b) {
    uint32_t const* A = reinterpret_cast<uint32_t const*>(a);
    uint32_t const* B = reinterpret_cast<uint32_t const*>(b);
    asm volatile(
        "mma.sync.aligned.m16n8k8.row.col.f32.tf32.tf32.f32 "
        "{%0,%1,%2,%3}, {%4,%5,%6,%7}, {%8,%9}, {%0,%1,%2,%3};"
        : "+f"(d[0]), "+f"(d[1]), "+f"(d[2]), "+f"(d[3])
        : "r"(A[0]), "r"(A[1]), "r"(A[2]), "r"(A[3]), "r"(B[0]), "r"(B[1]));
}

// ---------------------------------------------------------------------------
// 0) weight conversion to tf32 (rna)
// ---------------------------------------------------------------------------
__global__ void cvtw_kernel(const float* __restrict__ src, float* __restrict__ dst, int n)
{
    int i = blockIdx.x * blockDim.x + threadIdx.x;
    if (i < n) dst[i] = tf32_rna(src[i]);
}

// ---------------------------------------------------------------------------
// 1) depthwise 3x3 conv PE + residual -> windowed (wi,n,c)
// ---------------------------------------------------------------------------
__global__ void conv_pe_kernel(const float* __restrict__ x,
                               const float* __restrict__ cw,
                               const float* __restrict__ cb,
                               float* __restrict__ X0)
{
    const int cg = blockIdx.x * 8;
    const int h  = blockIdx.y;
    const int b  = blockIdx.z;

    __shared__ float sm[8][3][58];

    const int tid = threadIdx.y * 8 + threadIdx.x;
    const int lc  = tid / 56;
    const int lw  = tid % 56;

    const float* xp = x + ((size_t)(b * DIM + cg + lc) * HH) * WW;
#pragma unroll
    for (int r = 0; r < 3; r++) {
        int hh = h - 1 + r;
        float v = (hh >= 0 && hh < HH) ? xp[hh * WW + lw] : 0.0f;
        sm[lc][r][lw + 1] = v;
        if (lw == 0)  sm[lc][r][0]  = 0.0f;
        if (lw == 55) sm[lc][r][57] = 0.0f;
    }
    __syncthreads();

    const int c = threadIdx.x;
    const int w = threadIdx.y;

    float wreg[9];
    const float* cwp = cw + (size_t)(cg + c) * 9;
#pragma unroll
    for (int i = 0; i < 9; i++) wreg[i] = cwp[i];

    float pe = 0.0f;
#pragma unroll
    for (int kh = 0; kh < 3; kh++)
#pragma unroll
        for (int kw = 0; kw < 3; kw++)
            pe += wreg[kh * 3 + kw] * sm[c][kh][w + kw];

    float val = sm[c][1][w + 1] + pe + cb[cg + c];

    const int wi = (b * 4 + h / WS) * 4 + (w / WS);
    const int n  = (h % WS) * WS + (w % WS);
    X0[((size_t)wi * NTOK + n) * DIM + cg + c] = val;
}

// ---------------------------------------------------------------------------
// 2) LayerNorm; output tf32-rounded
// ---------------------------------------------------------------------------
__global__ void ln_kernel(const float* __restrict__ X,
                          const float* __restrict__ gamma,
                          const float* __restrict__ beta,
                          float* __restrict__ Y)
{
    const int warp = (blockIdx.x * blockDim.x + threadIdx.x) >> 5;
    const int lane = threadIdx.x & 31;
    if (warp >= TOK) return;

    const float* xp = X + (size_t)warp * DIM;
    float v[12];
    float s = 0.0f;
#pragma unroll
    for (int k = 0; k < 12; k++) { v[k] = xp[lane + 32 * k]; s += v[k]; }
#pragma unroll
    for (int o = 16; o; o >>= 1) s += __shfl_xor_sync(0xffffffffu, s, o);
    const float mean = s * (1.0f / DIM);

    float q = 0.0f;
#pragma unroll
    for (int k = 0; k < 12; k++) { float d = v[k] - mean; q += d * d; }
#pragma unroll
    for (int o = 16; o; o >>= 1) q += __shfl_xor_sync(0xffffffffu, q, o);
    const float inv = rsqrtf(q * (1.0f / DIM) + 1e-5f);

    float* yp = Y + (size_t)warp * DIM;
#pragma unroll
    for (int k = 0; k < 12; k++) {
        int c = lane + 32 * k;
        yp[c] = tf32_rna((v[k] - mean) * inv * gamma[c] + beta[c]);
    }
}

// ---------------------------------------------------------------------------
// 3) TF32 mma.sync GEMM: C[M,N] = act(A[M,K] @ W[N,K]^T + bias) (+ R)
//    CTA 256x128, BK=32, 8 warps, warp 64x64, 3-stage cp.async, 1 sync/iter.
// ---------------------------------------------------------------------------
#define BM 256
#define BN 128
#define BK 32
#define ASTR 36
#define A_ST_FL (BM * ASTR)
#define B_ST_FL (BN * ASTR)
#define STAGE_FL (A_ST_FL + B_ST_FL)
#define GEMM_SMEM (3 * STAGE_FL * 4)

__global__ __launch_bounds__(256, 1)
void mma_gemm_kernel(const float* __restrict__ A,
                     const float* __restrict__ W,
                     const float* __restrict__ bias,
                     const float* __restrict__ R,
                     float* __restrict__ C,
                     int M, int N, int K, int act)
{
    extern __shared__ float sm[];
    const int tid  = threadIdx.x;
    const int lane = tid & 31;
    const int wid  = tid >> 5;
    const int bm = blockIdx.y * BM;
    const int bn = blockIdx.x * BN;

    const int warp_m = (wid & 3) * 64;
    const int warp_n = (wid >> 2) * 64;

    const uint32_t smem_base = smem_u32(sm);

    float acc[4][8][4];
#pragma unroll
    for (int im = 0; im < 4; im++)
#pragma unroll
        for (int in = 0; in < 8; in++)
#pragma unroll
            for (int j = 0; j < 4; j++) acc[im][in][j] = 0.0f;

    const int lr = tid >> 3;
    const int lc = tid & 7;

    const int NC = K >> 5;

    auto fill = [&](int kc, int st) {
        const int k0 = kc << 5;
        const uint32_t abase = smem_base + (uint32_t)(st * STAGE_FL) * 4;
        const uint32_t bbase = abase + A_ST_FL * 4;
        const float* Ag = A + (size_t)(bm + lr) * K + k0 + lc * 4;
        const float* Wg = W + (size_t)(bn + lr) * K + k0 + lc * 4;
#pragma unroll
        for (int i = 0; i < 8; i++)
            cp16(abase + (uint32_t)(((lr + 32 * i) * ASTR + lc * 4) * 4), Ag + (size_t)32 * i * K);
#pragma unroll
        for (int i = 0; i < 4; i++)
            cp16(bbase + (uint32_t)(((lr + 32 * i) * ASTR + lc * 4) * 4), Wg + (size_t)32 * i * K);
    };

    fill(0, 0); CP_COMMIT();
    fill(1, 1); CP_COMMIT();

    for (int kc = 0; kc < NC; kc++) {
        CP_WAIT1();
        __syncthreads();

        // prefetch stage kc+2 (overwrites stage consumed at kc-1: safe after the sync)
        if (kc + 2 < NC) { fill(kc + 2, (kc + 2) % 3); CP_COMMIT(); }

        const int st = kc % 3;
        const float* As = sm + st * STAGE_FL;
        const float* Bs = As + A_ST_FL;
        const int rq = lane >> 2;
        const int kq = lane & 3;

#pragma unroll
        for (int s = 0; s < 4; s++) {
            const int k0 = s * 8 + kq;
            float a[4][4], b[8][2];
#pragma unroll
            for (int im = 0; im < 4; im++) {
                const float* ap = As + (warp_m + im * 16 + rq) * ASTR + k0;
                a[im][0] = ap[0];
                a[im][1] = ap[8 * ASTR];
                a[im][2] = ap[4];
                a[im][3] = ap[8 * ASTR + 4];
            }
#pragma unroll
            for (int in = 0; in < 8; in++) {
                const float* bp = Bs + (warp_n + in * 8 + rq) * ASTR + k0;
                b[in][0] = bp[0];
                b[in][1] = bp[4];
            }
#pragma unroll
            for (int im = 0; im < 4; im++)
#pragma unroll
                for (int in = 0; in < 8; in++)
                    mma_tf32(acc[im][in], a[im], b[in]);
        }
    }

    // epilogue
    const int rq = lane >> 2;
    const int cq = (lane & 3) * 2;
#pragma unroll
    for (int im = 0; im < 4; im++) {
        const int row0 = bm + warp_m + im * 16 + rq;
#pragma unroll
        for (int in = 0; in < 8; in++) {
            const int col = bn + warp_n + in * 8 + cq;
            const float2 bv = *(const float2*)(bias + col);
            float v0 = acc[im][in][0] + bv.x;
            float v1 = acc[im][in][1] + bv.y;
            float v2 = acc[im][in][2] + bv.x;
            float v3 = acc[im][in][3] + bv.y;
            if (act == 1) {
                v0 = tf32_rna(0.5f * v0 * (1.0f + erff(v0 * 0.70710678118654752f)));
                v1 = tf32_rna(0.5f * v1 * (1.0f + erff(v1 * 0.70710678118654752f)));
                v2 = tf32_rna(0.5f * v2 * (1.0f + erff(v2 * 0.70710678118654752f)));
                v3 = tf32_rna(0.5f * v3 * (1.0f + erff(v3 * 0.70710678118654752f)));
            }
            if (R) {
                const float2 r0 = *(const float2*)(R + (size_t)row0 * N + col);
                const float2 r1 = *(const float2*)(R + (size_t)(row0 + 8) * N + col);
                v0 += r0.x; v1 += r0.y; v2 += r1.x; v3 += r1.y;
            }
            *(float2*)(C + (size_t)row0 * N + col)       = make_float2(v0, v1);
            *(float2*)(C + (size_t)(row0 + 8) * N + col) = make_float2(v2, v3);
        }
    }
}

// ---------------------------------------------------------------------------
// 4) Window attention via mma.sync tf32.
//    CTA = one (window, head); 256 threads (8 warps).
//    Q/K/V in SMEM padded to 208 rows; strides: Q/K 36, V 40 (bank-conflict-free
//    fragment loads). S per warp-m-tile in regs; softmax; P via per-warp SMEM
//    buffer (stride 204) -> A-fragments for P@V.
// ---------------------------------------------------------------------------
#define QK_STR 36
#define V_STR  40
#define P_STR  204
#define MROWS  208
#define ATTN_SMEM ((2 * MROWS * QK_STR + MROWS * V_STR + 8 * 16 * P_STR) * 4)

__global__ __launch_bounds__(256, 1)
void attn_mma_kernel(const float* __restrict__ QKV, float* __restrict__ ATT)
{
    const int wi  = blockIdx.x / NH;
    const int hdi = blockIdx.x % NH;

    extern __shared__ float sh[];
    float* qs = sh;                          // 208 x 36
    float* ks = qs + MROWS * QK_STR;         // 208 x 36
    float* vs = ks + MROWS * QK_STR;         // 208 x 40
    float* ps = vs + MROWS * V_STR;          // 8 x 16 x 204

    const int tid  = threadIdx.x;
    const int warp = tid >> 5;
    const int lane = tid & 31;
    const int rq = lane >> 2;       // 0..7
    const int kq = lane & 3;        // 0..3
    const float scale = 0.1767766952966369f;   // 1/sqrt(32)

    // ---- load Q (pre-scaled), K, V; rows >=196 zero; tf32-rounded ----
    const float* base = QKV + (size_t)wi * NTOK * (3 * DIM) + hdi * HD;
    for (int idx = tid; idx < MROWS * 8; idx += 256) {
        const int n = idx >> 3, f4 = idx & 7;
        float4 q = make_float4(0.f, 0.f, 0.f, 0.f), k = q, v = q;
        if (n < NTOK) {
            const float* src = base + (size_t)n * (3 * DIM) + f4 * 4;
            q = *(const float4*)(src);
            k = *(const float4*)(src + DIM);
            v = *(const float4*)(src + 2 * DIM);
            q.x = tf32_rna(q.x * scale); q.y = tf32_rna(q.y * scale);
            q.z = tf32_rna(q.z * scale); q.w = tf32_rna(q.w * scale);
            k.x = tf32_rna(k.x); k.y = tf32_rna(k.y);
            k.z = tf32_rna(k.z); k.w = tf32_rna(k.w);
            v.x = tf32_rna(v.x); v.y = tf32_rna(v.y);
            v.z = tf32_rna(v.z); v.w = tf32_rna(v.w);
        }
        *(float4*)(qs + n * QK_STR + f4 * 4) = q;
        *(float4*)(ks + n * QK_STR + f4 * 4) = k;
        *(float4*)(vs + n * V_STR  + f4 * 4) = v;
    }
    __syncthreads();

    float* pw = ps + warp * 16 * P_STR;
    const int cq = kq * 2;

    // m-tiles 0..12 (rows 0..207); warp w handles tiles w and w+8 (if <13)
    for (int t = warp; t < 13; t += 8) {
        const int m0 = t * 16;

        // ---- A fragments (Q), 4 k-steps ----
        float a[4][4];
#pragma unroll
        for (int s = 0; s < 4; s++) {
            const float* qp = qs + (m0 + rq) * QK_STR + s * 8 + kq;
            a[s][0] = qp[0];
            a[s][1] = qp[8 * QK_STR];
            a[s][2] = qp[4];
            a[s][3] = qp[8 * QK_STR + 4];
        }

        // ---- S = Q K^T : 25 n-tiles ----
        float c[25][4];
#pragma unroll
        for (int nt = 0; nt < 25; nt++) { c[nt][0] = c[nt][1] = c[nt][2] = c[nt][3] = 0.f; }
#pragma unroll
        for (int nt = 0; nt < 25; nt++) {
#pragma unroll
            for (int s = 0; s < 4; s++) {
                float b[2];
                const float* kp = ks + (nt * 8 + rq) * QK_STR + s * 8 + kq;
                b[0] = kp[0];
                b[1] = kp[4];
                mma_tf32(c[nt], a[s], b);
            }
        }

        // ---- masked softmax (rows m0+rq and m0+rq+8) ----
        float mx0 = -1e30f, mx1 = -1e30f;
#pragma unroll
        for (int nt = 0; nt < 25; nt++) {
            const int col = nt * 8 + cq;
            if (col < NTOK)     { mx0 = fmaxf(mx0, c[nt][0]); mx1 = fmaxf(mx1, c[nt][2]); }
            if (col + 1 < NTOK) { mx0 = fmaxf(mx0, c[nt][1]); mx1 = fmaxf(mx1, c[nt][3]); }
        }
        mx0 = fmaxf(mx0, __shfl_xor_sync(0xffffffffu, mx0, 1));
        mx0 = fmaxf(mx0, __shfl_xor_sync(0xffffffffu, mx0, 2));
        mx1 = fmaxf(mx1, __shfl_xor_sync(0xffffffffu, mx1, 1));
        mx1 = fmaxf(mx1, __shfl_xor_sync(0xffffffffu, mx1, 2));

        float sum0 = 0.f, sum1 = 0.f;
#pragma unroll
        for (int nt = 0; nt < 25; nt++) {
            const int col = nt * 8 + cq;
            float p0 = (col < NTOK)     ? __expf(c[nt][0] - mx0) : 0.f;
            float p1 = (col + 1 < NTOK) ? __expf(c[nt][1] - mx0) : 0.f;
            float p2 = (col < NTOK)     ? __expf(c[nt][2] - mx1) : 0.f;
            float p3 = (col + 1 < NTOK) ? __expf(c[nt][3] - mx1) : 0.f;
            sum0 += p0 + p1;
            sum1 += p2 + p3;
            c[nt][0] = tf32_rna(p0); c[nt][1] = tf32_rna(p1);
            c[nt][2] = tf32_rna(p2); c[nt][3] = tf32_rna(p3);
        }
        sum0 += __shfl_xor_sync(0xffffffffu, sum0, 1);
        sum0 += __shfl_xor_sync(0xffffffffu, sum0, 2);
        sum1 += __shfl_xor_sync(0xffffffffu, sum1, 1);
        sum1 += __shfl_xor_sync(0xffffffffu, sum1, 2);

        // ---- stage P (unnormalized) in per-warp smem ----
#pragma unroll
        for (int nt = 0; nt < 25; nt++) {
            *(float2*)(pw + rq * P_STR + nt * 8 + cq)       = make_float2(c[nt][0], c[nt][1]);
            *(float2*)(pw + (rq + 8) * P_STR + nt * 8 + cq) = make_float2(c[nt][2], c[nt][3]);
        }
        __syncwarp();

        // ---- O = P V : K=200 (25 k-steps), N=32 (4 n-tiles) ----
        float o[4][4];
#pragma unroll
        for (int n = 0; n < 4; n++) { o[n][0] = o[n][1] = o[n][2] = o[n][3] = 0.f; }
#pragma unroll
        for (int kt = 0; kt < 25; kt++) {
            float a2[4];
            const float* pp = pw + rq * P_STR + kt * 8 + kq;
            a2[0] = pp[0];
            a2[1] = pp[8 * P_STR];
            a2[2] = pp[4];
            a2[3] = pp[8 * P_STR + 4];
#pragma unroll
            for (int n = 0; n < 4; n++) {
                float b[2];
                const float* vp = vs + (kt * 8 + kq) * V_STR + n * 8 + rq;
                b[0] = vp[0];
                b[1] = vp[4 * V_STR];
                mma_tf32(o[n], a2, b);
            }
        }
        __syncwarp();

        // ---- normalize + store (tf32-rounded: consumed as GEMM A operand) ----
        const float inv0 = 1.0f / sum0;
        const float inv1 = 1.0f / sum1;
        const int r0 = m0 + rq, r1 = m0 + rq + 8;
#pragma unroll
        for (int n = 0; n < 4; n++) {
            const int col = hdi * HD + n * 8 + cq;
            if (r0 < NTOK)
                *(float2*)(ATT + ((size_t)wi * NTOK + r0) * DIM + col) =
                    make_float2(tf32_rna(o[n][0] * inv0), tf32_rna(o[n][1] * inv0));
            if (r1 < NTOK)
                *(float2*)(ATT + ((size_t)wi * NTOK + r1) * DIM + col) =
                    make_float2(tf32_rna(o[n][2] * inv1), tf32_rna(o[n][3] * inv1));
        }
    }
}

// ---------------------------------------------------------------------------
// 5) Windowed (wi,n,c) -> BCHW output
// ---------------------------------------------------------------------------
__global__ void unwin_kernel(const float* __restrict__ X,
                             float* __restrict__ out)
{
    const int ct = blockIdx.x >> 1, wt = blockIdx.x & 1;
    const int h = blockIdx.y, b = blockIdx.z;
    const int c0 = ct * 32, w0 = wt * 32;

    __shared__ float sm[32][33];
    const int tx = threadIdx.x, ty = threadIdx.y;

#pragma unroll
    for (int k = 0; k < 4; k++) {
        int r = ty + 8 * k;
        int w = w0 + r;
        if (w < WW) {
            int wi = (b * 4 + h / WS) * 4 + w / WS;
            int n  = (h % WS) * WS + (w % WS);
            sm[r][tx] = X[((size_t)wi * NTOK + n) * DIM + c0 + tx];
        }
    }
    __syncthreads();

#pragma unroll
    for (int k = 0; k < 4; k++) {
        int c = c0 + ty + 8 * k;
        int w = w0 + tx;
        if (w < WW)
            out[(((size_t)b * DIM + c) * HH + h) * WW + w] = sm[tx][ty + 8 * k];
    }
}

// ---------------------------------------------------------------------------
// Launch
// ---------------------------------------------------------------------------
extern "C" void kernel_launch(void* const* d_in, const int* in_sizes, int n_in,
                              void* d_out, int out_size)
{
    const float* x      = (const float*)d_in[0];
    const float* conv_w = (const float*)d_in[1];
    const float* conv_b = (const float*)d_in[2];
    const float* ln1_g  = (const float*)d_in[3];
    const float* ln1_b  = (const float*)d_in[4];
    const float* qkv_w  = (const float*)d_in[5];
    const float* qkv_b  = (const float*)d_in[6];
    const float* proj_w = (const float*)d_in[7];
    const float* proj_b = (const float*)d_in[8];
    const float* ln2_g  = (const float*)d_in[9];
    const float* ln2_b  = (const float*)d_in[10];
    const float* fc1_w  = (const float*)d_in[11];
    const float* fc1_b  = (const float*)d_in[12];
    const float* fc2_w  = (const float*)d_in[13];
    const float* fc2_b  = (const float*)d_in[14];
    float* out = (float*)d_out;

    float *X0, *Y, *QKV, *ATT, *X1, *F, *Wc;
    cudaGetSymbolAddress((void**)&X0,  g_X0);
    cudaGetSymbolAddress((void**)&Y,   g_Y);
    cudaGetSymbolAddress((void**)&QKV, g_QKV);
    cudaGetSymbolAddress((void**)&ATT, g_ATT);
    cudaGetSymbolAddress((void**)&X1,  g_X1);
    cudaGetSymbolAddress((void**)&F,   g_F);
    cudaGetSymbolAddress((void**)&Wc,  g_Wc);

    cudaFuncSetAttribute(attn_mma_kernel, cudaFuncAttributeMaxDynamicSharedMemorySize, ATTN_SMEM);
    cudaFuncSetAttribute(mma_gemm_kernel, cudaFuncAttributeMaxDynamicSharedMemorySize, GEMM_SMEM);

    // 0) tf32-round weights
    cvtw_kernel<<<(3 * DIM * DIM + 255) / 256, 256>>>(qkv_w,  Wc + WOFF_QKV,  3 * DIM * DIM);
    cvtw_kernel<<<(DIM * DIM + 255) / 256, 256>>>(proj_w, Wc + WOFF_PROJ, DIM * DIM);
    cvtw_kernel<<<(4 * DIM * DIM + 255) / 256, 256>>>(fc1_w,  Wc + WOFF_FC1,  4 * DIM * DIM);
    cvtw_kernel<<<(4 * DIM * DIM + 255) / 256, 256>>>(fc2_w,  Wc + WOFF_FC2,  4 * DIM * DIM);

    // 1) conv PE + residual -> X0
    conv_pe_kernel<<<dim3(DIM / 8, HH, BATCH), dim3(8, 56)>>>(x, conv_w, conv_b, X0);

    // 2) LN1 -> Y
    ln_kernel<<<TOK / 8, 256>>>(X0, ln1_g, ln1_b, Y);

    // 3) QKV GEMM
    mma_gemm_kernel<<<dim3(3 * DIM / BN, TOK / BM), 256, GEMM_SMEM>>>(
        Y, Wc + WOFF_QKV, qkv_b, nullptr, QKV, TOK, 3 * DIM, DIM, 0);

    // 4) window attention (tensor cores)
    attn_mma_kernel<<<NWIN * NH, 256, ATTN_SMEM>>>(QKV, ATT);

    // 5) proj GEMM + residual(X0) -> X1
    mma_gemm_kernel<<<dim3(DIM / BN, TOK / BM), 256, GEMM_SMEM>>>(
        ATT, Wc + WOFF_PROJ, proj_b, X0, X1, TOK, DIM, DIM, 0);

    // 6) LN2 -> Y
    ln_kernel<<<TOK / 8, 256>>>(X1, ln2_g, ln2_b, Y);

    // 7) FC1 GEMM + GELU -> F
    mma_gemm_kernel<<<dim3(4 * DIM / BN, TOK / BM), 256, GEMM_SMEM>>>(
        Y, Wc + WOFF_FC1, fc1_b, nullptr, F, TOK, 4 * DIM, DIM, 1);

    // 8) FC2 GEMM + residual(X1) -> X0
    mma_gemm_kernel<<<dim3(DIM / BN, TOK / BM), 256, GEMM_SMEM>>>(
        F, Wc + WOFF_FC2, fc2_b, X1, X0, TOK, DIM, 4 * DIM, 0);

    // 9) un-window -> BCHW
    unwin_kernel<<<dim3(24, HH, BATCH), dim3(32, 8)>>>(X0, out);
}

// round 5
// speedup vs baseline: 3.8257x; 1.1993x over previous
#include <cuda_runtime.h>
#include <cuda_bf16.h>
#include <cuda_fp16.h>
#include <math.h>
#include <cstdint>

// ---------------------------------------------------------------------------
// Problem constants
// ---------------------------------------------------------------------------
#define DIM   384
#define NH    12
#define HD    32
#define WS    14
#define BATCH 16
#define HH    56
#define WW    56
#define NWIN  256
#define NTOK  196
#define TOK   50176          // NWIN*NTOK

// ---------------------------------------------------------------------------
// Scratch
// ---------------------------------------------------------------------------
__device__ __align__(16) float  g_X0 [(size_t)TOK * DIM];
__device__ __align__(16) __half g_Y  [(size_t)TOK * DIM];
__device__ __align__(16) float  g_QKV[(size_t)TOK * 3 * DIM];
__device__ __align__(16) __half g_ATT[(size_t)TOK * DIM];
__device__ __align__(16) float  g_X1 [(size_t)TOK * DIM];
__device__ __align__(16) __half g_F  [(size_t)TOK * 4 * DIM];
__device__ __align__(16) __half g_Wh [1769472];          // fp16 weights

#define WOFF_QKV  0
#define WOFF_PROJ (3 * DIM * DIM)
#define WOFF_FC1  (WOFF_PROJ + DIM * DIM)
#define WOFF_FC2  (WOFF_FC1 + 4 * DIM * DIM)

// ---------------------------------------------------------------------------
// helpers
// ---------------------------------------------------------------------------
__device__ __forceinline__ float tf32_rna(float x) {
    uint32_t u;
    asm("cvt.rna.tf32.f32 %0, %1;" : "=r"(u) : "f"(x));
    return __uint_as_float(u);
}
__device__ __forceinline__ uint32_t smem_u32(const void* p) {
    uint32_t a;
    asm("{ .reg .u64 t; cvta.to.shared.u64 t, %1; cvt.u32.u64 %0, t; }" : "=r"(a) : "l"(p));
    return a;
}
__device__ __forceinline__ void cp16(uint32_t dst, const void* src) {
    asm volatile("cp.async.cg.shared.global [%0], [%1], 16;" :: "r"(dst), "l"(src));
}
#define CP_COMMIT() asm volatile("cp.async.commit_group;" ::: "memory")
#define CP_WAIT3()  asm volatile("cp.async.wait_group 3;" ::: "memory")

__device__ __forceinline__ void ldsm_x4(uint32_t* r, uint32_t a) {
    asm volatile("ldmatrix.sync.aligned.m8n8.x4.shared.b16 {%0,%1,%2,%3}, [%4];"
                 : "=r"(r[0]), "=r"(r[1]), "=r"(r[2]), "=r"(r[3]) : "r"(a));
}
__device__ __forceinline__ void mma_f16(float* d, const uint32_t* a, const uint32_t* b) {
    asm volatile(
        "mma.sync.aligned.m16n8k16.row.col.f32.f16.f16.f32 "
        "{%0,%1,%2,%3}, {%4,%5,%6,%7}, {%8,%9}, {%0,%1,%2,%3};"
        : "+f"(d[0]), "+f"(d[1]), "+f"(d[2]), "+f"(d[3])
        : "r"(a[0]), "r"(a[1]), "r"(a[2]), "r"(a[3]), "r"(b[0]), "r"(b[1]));
}
__device__ __forceinline__ void mma_tf32(float* d, const float* a, const float* b) {
    uint32_t const* A = reinterpret_cast<uint32_t const*>(a);
    uint32_t const* B = reinterpret_cast<uint32_t const*>(b);
    asm volatile(
        "mma.sync.aligned.m16n8k8.row.col.f32.tf32.tf32.f32 "
        "{%0,%1,%2,%3}, {%4,%5,%6,%7}, {%8,%9}, {%0,%1,%2,%3};"
        : "+f"(d[0]), "+f"(d[1]), "+f"(d[2]), "+f"(d[3])
        : "r"(A[0]), "r"(A[1]), "r"(A[2]), "r"(A[3]), "r"(B[0]), "r"(B[1]));
}

// ---------------------------------------------------------------------------
// 0) weight conversion fp32 -> fp16
// ---------------------------------------------------------------------------
__global__ void cvtw_kernel(const float* __restrict__ src, __half* __restrict__ dst, int n)
{
    int i = blockIdx.x * blockDim.x + threadIdx.x;
    if (i < n) dst[i] = __float2half_rn(src[i]);
}

// ---------------------------------------------------------------------------
// 1) depthwise 3x3 conv PE + residual -> windowed (wi,n,c)
// ---------------------------------------------------------------------------
__global__ void conv_pe_kernel(const float* __restrict__ x,
                               const float* __restrict__ cw,
                               const float* __restrict__ cb,
                               float* __restrict__ X0)
{
    const int cg = blockIdx.x * 8;
    const int h  = blockIdx.y;
    const int b  = blockIdx.z;

    __shared__ float sm[8][3][58];

    const int tid = threadIdx.y * 8 + threadIdx.x;
    const int lc  = tid / 56;
    const int lw  = tid % 56;

    const float* xp = x + ((size_t)(b * DIM + cg + lc) * HH) * WW;
#pragma unroll
    for (int r = 0; r < 3; r++) {
        int hh = h - 1 + r;
        float v = (hh >= 0 && hh < HH) ? xp[hh * WW + lw] : 0.0f;
        sm[lc][r][lw + 1] = v;
        if (lw == 0)  sm[lc][r][0]  = 0.0f;
        if (lw == 55) sm[lc][r][57] = 0.0f;
    }
    __syncthreads();

    const int c = threadIdx.x;
    const int w = threadIdx.y;

    float wreg[9];
    const float* cwp = cw + (size_t)(cg + c) * 9;
#pragma unroll
    for (int i = 0; i < 9; i++) wreg[i] = cwp[i];

    float pe = 0.0f;
#pragma unroll
    for (int kh = 0; kh < 3; kh++)
#pragma unroll
        for (int kw = 0; kw < 3; kw++)
            pe += wreg[kh * 3 + kw] * sm[c][kh][w + kw];

    float val = sm[c][1][w + 1] + pe + cb[cg + c];

    const int wi = (b * 4 + h / WS) * 4 + (w / WS);
    const int n  = (h % WS) * WS + (w % WS);
    X0[((size_t)wi * NTOK + n) * DIM + cg + c] = val;
}

// ---------------------------------------------------------------------------
// 2) LayerNorm; fp16 output (GEMM A operand)
// ---------------------------------------------------------------------------
__global__ void ln_kernel(const float* __restrict__ X,
                          const float* __restrict__ gamma,
                          const float* __restrict__ beta,
                          __half* __restrict__ Y)
{
    const int warp = (blockIdx.x * blockDim.x + threadIdx.x) >> 5;
    const int lane = threadIdx.x & 31;
    if (warp >= TOK) return;

    const float* xp = X + (size_t)warp * DIM;
    float v[12];
    float s = 0.0f;
#pragma unroll
    for (int k = 0; k < 12; k++) { v[k] = xp[lane + 32 * k]; s += v[k]; }
#pragma unroll
    for (int o = 16; o; o >>= 1) s += __shfl_xor_sync(0xffffffffu, s, o);
    const float mean = s * (1.0f / DIM);

    float q = 0.0f;
#pragma unroll
    for (int k = 0; k < 12; k++) { float d = v[k] - mean; q += d * d; }
#pragma unroll
    for (int o = 16; o; o >>= 1) q += __shfl_xor_sync(0xffffffffu, q, o);
    const float inv = rsqrtf(q * (1.0f / DIM) + 1e-5f);

    __half* yp = Y + (size_t)warp * DIM;
#pragma unroll
    for (int k = 0; k < 12; k++) {
        int c = lane + 32 * k;
        yp[c] = __float2half_rn((v[k] - mean) * inv * gamma[c] + beta[c]);
    }
}

// ---------------------------------------------------------------------------
// 3) FP16 mma.sync GEMM: C[M,N] = act(A[M,K] @ W[N,K]^T + bias) (+ R)
//    CTA 256x128, BK=32, 8 warps (4m x 2n), warp 64x64.
//    5-stage cp.async, ldmatrix.x4 fragment loads (swizzled, conflict-free).
//    Output: fp32 (+residual) via Cf, OR fp16 via Ch (gelu allowed on both).
// ---------------------------------------------------------------------------
#define BM 256
#define BN 128
#define BK 32
#define A_BYTES 16384                        // 256 rows x 64B
#define STAGE_B 24576                        // A 16K + B 8K
#define NSTAGE  5
#define GEMM_SMEM (NSTAGE * STAGE_B)         // 122880

__global__ __launch_bounds__(256, 1)
void hgemm_kernel(const __half* __restrict__ A,
                  const __half* __restrict__ W,
                  const float* __restrict__ bias,
                  const float* __restrict__ R,
                  float* __restrict__ Cf,
                  __half* __restrict__ Ch,
                  int M, int N, int K, int act)
{
    extern __shared__ char smc[];
    const uint32_t smem_base = smem_u32(smc);
    const int tid  = threadIdx.x;
    const int lane = tid & 31;
    const int wid  = tid >> 5;
    const int bm = blockIdx.y * BM;
    const int bn = blockIdx.x * BN;

    const int warp_m = (wid & 3) * 64;
    const int warp_n = (wid >> 2) * 64;

    float acc[4][8][4];
#pragma unroll
    for (int im = 0; im < 4; im++)
#pragma unroll
        for (int in = 0; in < 8; in++)
#pragma unroll
            for (int j = 0; j < 4; j++) acc[im][in][j] = 0.0f;

    // ldmatrix lane geometry
    const int g  = lane >> 3;
    const int r8 = lane & 7;
    const int a_row = warp_m + (g & 1) * 8 + r8;     // + im*16
    const int a_sw  = (a_row >> 1) & 3;
    const int a_cg  = g >> 1;
    const int b_row = warp_n + (g >> 1) * 8 + r8;    // + inp*16
    const int b_sw  = (b_row >> 1) & 3;
    const int b_cg  = g & 1;

    const int NC = K >> 5;

    // fill: thread t loads A row t (4 chunks) and B row t>>1 (2 chunks)
    const int br  = tid >> 1;
    const int bc0 = (tid & 1) * 2;
    auto fill = [&](int kc, int st) {
        const int k0 = kc << 5;
        const uint32_t sb = smem_base + (uint32_t)st * STAGE_B;
        const __half* Ag = A + (size_t)(bm + tid) * K + k0;
#pragma unroll
        for (int c = 0; c < 4; c++)
            cp16(sb + (uint32_t)(tid * 64 + ((c ^ ((tid >> 1) & 3)) * 16)), Ag + c * 8);
        const __half* Wg = W + (size_t)(bn + br) * K + k0;
#pragma unroll
        for (int c = 0; c < 2; c++) {
            const int cc = bc0 + c;
            cp16(sb + A_BYTES + (uint32_t)(br * 64 + ((cc ^ ((br >> 1) & 3)) * 16)), Wg + cc * 8);
        }
    };

    fill(0, 0); CP_COMMIT();
    fill(1, 1); CP_COMMIT();
    fill(2, 2); CP_COMMIT();
    fill(3, 3); CP_COMMIT();

    for (int kc = 0; kc < NC; kc++) {
        CP_WAIT3();
        __syncthreads();

        if (kc + 4 < NC) fill(kc + 4, (kc + 4) % NSTAGE);
        CP_COMMIT();                      // unconditional: constant pipeline depth

        const uint32_t ab = smem_base + (uint32_t)(kc % NSTAGE) * STAGE_B;
        const uint32_t bb = ab + A_BYTES;

#pragma unroll
        for (int s = 0; s < 2; s++) {
            uint32_t af[4][4], bf[4][4];
#pragma unroll
            for (int im = 0; im < 4; im++)
                ldsm_x4(af[im], ab + (uint32_t)(a_row * 64 + im * 1024 +
                                                (((s * 2 + a_cg) ^ a_sw) * 16)));
#pragma unroll
            for (int inp = 0; inp < 4; inp++)
                ldsm_x4(bf[inp], bb + (uint32_t)(b_row * 64 + inp * 1024 +
                                                 (((s * 2 + b_cg) ^ b_sw) * 16)));
#pragma unroll
            for (int im = 0; im < 4; im++)
#pragma unroll
                for (int in = 0; in < 8; in++)
                    mma_f16(acc[im][in], af[im], &bf[in >> 1][(in & 1) * 2]);
        }
    }

    // epilogue
    const int rq = lane >> 2;
    const int cq = (lane & 3) * 2;
#pragma unroll
    for (int im = 0; im < 4; im++) {
        const int row0 = bm + warp_m + im * 16 + rq;
#pragma unroll
        for (int in = 0; in < 8; in++) {
            const int col = bn + warp_n + in * 8 + cq;
            const float2 bv = *(const float2*)(bias + col);
            float v0 = acc[im][in][0] + bv.x;
            float v1 = acc[im][in][1] + bv.y;
            float v2 = acc[im][in][2] + bv.x;
            float v3 = acc[im][in][3] + bv.y;
            if (act == 1) {
                v0 = 0.5f * v0 * (1.0f + erff(v0 * 0.70710678118654752f));
                v1 = 0.5f * v1 * (1.0f + erff(v1 * 0.70710678118654752f));
                v2 = 0.5f * v2 * (1.0f + erff(v2 * 0.70710678118654752f));
                v3 = 0.5f * v3 * (1.0f + erff(v3 * 0.70710678118654752f));
            }
            if (Ch) {
                *(__half2*)(Ch + (size_t)row0 * N + col) =
                    __halves2half2(__float2half_rn(v0), __float2half_rn(v1));
                *(__half2*)(Ch + (size_t)(row0 + 8) * N + col) =
                    __halves2half2(__float2half_rn(v2), __float2half_rn(v3));
            } else {
                if (R) {
                    const float2 r0 = *(const float2*)(R + (size_t)row0 * N + col);
                    const float2 r1 = *(const float2*)(R + (size_t)(row0 + 8) * N + col);
                    v0 += r0.x; v1 += r0.y; v2 += r1.x; v3 += r1.y;
                }
                *(float2*)(Cf + (size_t)row0 * N + col)       = make_float2(v0, v1);
                *(float2*)(Cf + (size_t)(row0 + 8) * N + col) = make_float2(v2, v3);
            }
        }
    }
}

// ---------------------------------------------------------------------------
// 4) Window attention via mma.sync tf32 (unchanged math), fp16 output.
// ---------------------------------------------------------------------------
#define QK_STR 36
#define V_STR  40
#define P_STR  204
#define MROWS  208
#define ATTN_SMEM ((2 * MROWS * QK_STR + MROWS * V_STR + 8 * 16 * P_STR) * 4)

__global__ __launch_bounds__(256, 1)
void attn_mma_kernel(const float* __restrict__ QKV, __half* __restrict__ ATT)
{
    const int wi  = blockIdx.x / NH;
    const int hdi = blockIdx.x % NH;

    extern __shared__ float sh[];
    float* qs = sh;
    float* ks = qs + MROWS * QK_STR;
    float* vs = ks + MROWS * QK_STR;
    float* ps = vs + MROWS * V_STR;

    const int tid  = threadIdx.x;
    const int warp = tid >> 5;
    const int lane = tid & 31;
    const int rq = lane >> 2;
    const int kq = lane & 3;
    const float scale = 0.1767766952966369f;

    const float* base = QKV + (size_t)wi * NTOK * (3 * DIM) + hdi * HD;
    for (int idx = tid; idx < MROWS * 8; idx += 256) {
        const int n = idx >> 3, f4 = idx & 7;
        float4 q = make_float4(0.f, 0.f, 0.f, 0.f), k = q, v = q;
        if (n < NTOK) {
            const float* src = base + (size_t)n * (3 * DIM) + f4 * 4;
            q = *(const float4*)(src);
            k = *(const float4*)(src + DIM);
            v = *(const float4*)(src + 2 * DIM);
            q.x = tf32_rna(q.x * scale); q.y = tf32_rna(q.y * scale);
            q.z = tf32_rna(q.z * scale); q.w = tf32_rna(q.w * scale);
            k.x = tf32_rna(k.x); k.y = tf32_rna(k.y);
            k.z = tf32_rna(k.z); k.w = tf32_rna(k.w);
            v.x = tf32_rna(v.x); v.y = tf32_rna(v.y);
            v.z = tf32_rna(v.z); v.w = tf32_rna(v.w);
        }
        *(float4*)(qs + n * QK_STR + f4 * 4) = q;
        *(float4*)(ks + n * QK_STR + f4 * 4) = k;
        *(float4*)(vs + n * V_STR  + f4 * 4) = v;
    }
    __syncthreads();

    float* pw = ps + warp * 16 * P_STR;
    const int cq2 = kq * 2;

    for (int t = warp; t < 13; t += 8) {
        const int m0 = t * 16;

        float a[4][4];
#pragma unroll
        for (int s = 0; s < 4; s++) {
            const float* qp = qs + (m0 + rq) * QK_STR + s * 8 + kq;
            a[s][0] = qp[0];
            a[s][1] = qp[8 * QK_STR];
            a[s][2] = qp[4];
            a[s][3] = qp[8 * QK_STR + 4];
        }

        float c[25][4];
#pragma unroll
        for (int nt = 0; nt < 25; nt++) { c[nt][0] = c[nt][1] = c[nt][2] = c[nt][3] = 0.f; }
#pragma unroll
        for (int nt = 0; nt < 25; nt++) {
#pragma unroll
            for (int s = 0; s < 4; s++) {
                float b[2];
                const float* kp = ks + (nt * 8 + rq) * QK_STR + s * 8 + kq;
                b[0] = kp[0];
                b[1] = kp[4];
                mma_tf32(c[nt], a[s], b);
            }
        }

        float mx0 = -1e30f, mx1 = -1e30f;
#pragma unroll
        for (int nt = 0; nt < 25; nt++) {
            const int col = nt * 8 + cq2;
            if (col < NTOK)     { mx0 = fmaxf(mx0, c[nt][0]); mx1 = fmaxf(mx1, c[nt][2]); }
            if (col + 1 < NTOK) { mx0 = fmaxf(mx0, c[nt][1]); mx1 = fmaxf(mx1, c[nt][3]); }
        }
        mx0 = fmaxf(mx0, __shfl_xor_sync(0xffffffffu, mx0, 1));
        mx0 = fmaxf(mx0, __shfl_xor_sync(0xffffffffu, mx0, 2));
        mx1 = fmaxf(mx1, __shfl_xor_sync(0xffffffffu, mx1, 1));
        mx1 = fmaxf(mx1, __shfl_xor_sync(0xffffffffu, mx1, 2));

        float sum0 = 0.f, sum1 = 0.f;
#pragma unroll
        for (int nt = 0; nt < 25; nt++) {
            const int col = nt * 8 + cq2;
            float p0 = (col < NTOK)     ? __expf(c[nt][0] - mx0) : 0.f;
            float p1 = (col + 1 < NTOK) ? __expf(c[nt][1] - mx0) : 0.f;
            float p2 = (col < NTOK)     ? __expf(c[nt][2] - mx1) : 0.f;
            float p3 = (col + 1 < NTOK) ? __expf(c[nt][3] - mx1) : 0.f;
            sum0 += p0 + p1;
            sum1 += p2 + p3;
            c[nt][0] = tf32_rna(p0); c[nt][1] = tf32_rna(p1);
            c[nt][2] = tf32_rna(p2); c[nt][3] = tf32_rna(p3);
        }
        sum0 += __shfl_xor_sync(0xffffffffu, sum0, 1);
        sum0 += __shfl_xor_sync(0xffffffffu, sum0, 2);
        sum1 += __shfl_xor_sync(0xffffffffu, sum1, 1);
        sum1 += __shfl_xor_sync(0xffffffffu, sum1, 2);

#pragma unroll
        for (int nt = 0; nt < 25; nt++) {
            *(float2*)(pw + rq * P_STR + nt * 8 + cq2)       = make_float2(c[nt][0], c[nt][1]);
            *(float2*)(pw + (rq + 8) * P_STR + nt * 8 + cq2) = make_float2(c[nt][2], c[nt][3]);
        }
        __syncwarp();

        float o[4][4];
#pragma unroll
        for (int n = 0; n < 4; n++) { o[n][0] = o[n][1] = o[n][2] = o[n][3] = 0.f; }
#pragma unroll
        for (int kt = 0; kt < 25; kt++) {
            float a2[4];
            const float* pp = pw + rq * P_STR + kt * 8 + kq;
            a2[0] = pp[0];
            a2[1] = pp[8 * P_STR];
            a2[2] = pp[4];
            a2[3] = pp[8 * P_STR + 4];
#pragma unroll
            for (int n = 0; n < 4; n++) {
                float b[2];
                const float* vp = vs + (kt * 8 + kq) * V_STR + n * 8 + rq;
                b[0] = vp[0];
                b[1] = vp[4 * V_STR];
                mma_tf32(o[n], a2, b);
            }
        }
        __syncwarp();

        const float inv0 = 1.0f / sum0;
        const float inv1 = 1.0f / sum1;
        const int r0 = m0 + rq, r1 = m0 + rq + 8;
#pragma unroll
        for (int n = 0; n < 4; n++) {
            const int col = hdi * HD + n * 8 + cq2;
            if (r0 < NTOK)
                *(__half2*)(ATT + ((size_t)wi * NTOK + r0) * DIM + col) =
                    __halves2half2(__float2half_rn(o[n][0] * inv0), __float2half_rn(o[n][1] * inv0));
            if (r1 < NTOK)
                *(__half2*)(ATT + ((size_t)wi * NTOK + r1) * DIM + col) =
                    __halves2half2(__float2half_rn(o[n][2] * inv1), __float2half_rn(o[n][3] * inv1));
        }
    }
}

// ---------------------------------------------------------------------------
// 5) Windowed (wi,n,c) -> BCHW output
// ---------------------------------------------------------------------------
__global__ void unwin_kernel(const float* __restrict__ X,
                             float* __restrict__ out)
{
    const int ct = blockIdx.x >> 1, wt = blockIdx.x & 1;
    const int h = blockIdx.y, b = blockIdx.z;
    const int c0 = ct * 32, w0 = wt * 32;

    __shared__ float sm[32][33];
    const int tx = threadIdx.x, ty = threadIdx.y;

#pragma unroll
    for (int k = 0; k < 4; k++) {
        int r = ty + 8 * k;
        int w = w0 + r;
        if (w < WW) {
            int wi = (b * 4 + h / WS) * 4 + w / WS;
            int n  = (h % WS) * WS + (w % WS);
            sm[r][tx] = X[((size_t)wi * NTOK + n) * DIM + c0 + tx];
        }
    }
    __syncthreads();

#pragma unroll
    for (int k = 0; k < 4; k++) {
        int c = c0 + ty + 8 * k;
        int w = w0 + tx;
        if (w < WW)
            out[(((size_t)b * DIM + c) * HH + h) * WW + w] = sm[tx][ty + 8 * k];
    }
}

// ---------------------------------------------------------------------------
// Launch
// ---------------------------------------------------------------------------
extern "C" void kernel_launch(void* const* d_in, const int* in_sizes, int n_in,
                              void* d_out, int out_size)
{
    const float* x      = (const float*)d_in[0];
    const float* conv_w = (const float*)d_in[1];
    const float* conv_b = (const float*)d_in[2];
    const float* ln1_g  = (const float*)d_in[3];
    const float* ln1_b  = (const float*)d_in[4];
    const float* qkv_w  = (const float*)d_in[5];
    const float* qkv_b  = (const float*)d_in[6];
    const float* proj_w = (const float*)d_in[7];
    const float* proj_b = (const float*)d_in[8];
    const float* ln2_g  = (const float*)d_in[9];
    const float* ln2_b  = (const float*)d_in[10];
    const float* fc1_w  = (const float*)d_in[11];
    const float* fc1_b  = (const float*)d_in[12];
    const float* fc2_w  = (const float*)d_in[13];
    const float* fc2_b  = (const float*)d_in[14];
    float* out = (float*)d_out;

    float *X0, *QKV, *X1;
    __half *Y, *ATT, *F, *Wh;
    cudaGetSymbolAddress((void**)&X0,  g_X0);
    cudaGetSymbolAddress((void**)&Y,   g_Y);
    cudaGetSymbolAddress((void**)&QKV, g_QKV);
    cudaGetSymbolAddress((void**)&ATT, g_ATT);
    cudaGetSymbolAddress((void**)&X1,  g_X1);
    cudaGetSymbolAddress((void**)&F,   g_F);
    cudaGetSymbolAddress((void**)&Wh,  g_Wh);

    cudaFuncSetAttribute(attn_mma_kernel, cudaFuncAttributeMaxDynamicSharedMemorySize, ATTN_SMEM);
    cudaFuncSetAttribute(hgemm_kernel, cudaFuncAttributeMaxDynamicSharedMemorySize, GEMM_SMEM);

    // 0) fp16 weights
    cvtw_kernel<<<(3 * DIM * DIM + 255) / 256, 256>>>(qkv_w,  Wh + WOFF_QKV,  3 * DIM * DIM);
    cvtw_kernel<<<(DIM * DIM + 255) / 256, 256>>>(proj_w, Wh + WOFF_PROJ, DIM * DIM);
    cvtw_kernel<<<(4 * DIM * DIM + 255) / 256, 256>>>(fc1_w,  Wh + WOFF_FC1,  4 * DIM * DIM);
    cvtw_kernel<<<(4 * DIM * DIM + 255) / 256, 256>>>(fc2_w,  Wh + WOFF_FC2,  4 * DIM * DIM);

    // 1) conv PE + residual -> X0
    conv_pe_kernel<<<dim3(DIM / 8, HH, BATCH), dim3(8, 56)>>>(x, conv_w, conv_b, X0);

    // 2) LN1 -> Y (fp16)
    ln_kernel<<<TOK / 8, 256>>>(X0, ln1_g, ln1_b, Y);

    // 3) QKV GEMM (fp16 in, fp32 out)
    hgemm_kernel<<<dim3(3 * DIM / BN, TOK / BM), 256, GEMM_SMEM>>>(
        Y, Wh + WOFF_QKV, qkv_b, nullptr, QKV, nullptr, TOK, 3 * DIM, DIM, 0);

    // 4) window attention -> ATT (fp16)
    attn_mma_kernel<<<NWIN * NH, 256, ATTN_SMEM>>>(QKV, ATT);

    // 5) proj GEMM + residual(X0) -> X1 (fp32)
    hgemm_kernel<<<dim3(DIM / BN, TOK / BM), 256, GEMM_SMEM>>>(
        ATT, Wh + WOFF_PROJ, proj_b, X0, X1, nullptr, TOK, DIM, DIM, 0);

    // 6) LN2 -> Y (fp16)
    ln_kernel<<<TOK / 8, 256>>>(X1, ln2_g, ln2_b, Y);

    // 7) FC1 GEMM + GELU -> F (fp16)
    hgemm_kernel<<<dim3(4 * DIM / BN, TOK / BM), 256, GEMM_SMEM>>>(
        Y, Wh + WOFF_FC1, fc1_b, nullptr, nullptr, F, TOK, 4 * DIM, DIM, 1);

    // 8) FC2 GEMM + residual(X1) -> X0 (fp32)
    hgemm_kernel<<<dim3(DIM / BN, TOK / BM), 256, GEMM_SMEM>>>(
        F, Wh + WOFF_FC2, fc2_b, X1, X0, nullptr, TOK, DIM, 4 * DIM, 0);

    // 9) un-window -> BCHW
    unwin_kernel<<<dim3(24, HH, BATCH), dim3(32, 8)>>>(X0, out);
}

// round 6
// speedup vs baseline: 4.5638x; 1.1929x over previous
#include <cuda_runtime.h>
#include <cuda_bf16.h>
#include <cuda_fp16.h>
#include <math.h>
#include <cstdint>

// ---------------------------------------------------------------------------
// Problem constants
// ---------------------------------------------------------------------------
#define DIM   384
#define NH    12
#define HD    32
#define WS    14
#define BATCH 16
#define HH    56
#define WW    56
#define NWIN  256
#define NTOK  196
#define TOK   50176          // NWIN*NTOK

// ---------------------------------------------------------------------------
// Scratch
// ---------------------------------------------------------------------------
__device__ __align__(16) float  g_X0 [(size_t)TOK * DIM];
__device__ __align__(16) __half g_Y  [(size_t)TOK * DIM];
__device__ __align__(16) __half g_QKV[(size_t)TOK * 3 * DIM];
__device__ __align__(16) __half g_ATT[(size_t)TOK * DIM];
__device__ __align__(16) float  g_X1 [(size_t)TOK * DIM];
__device__ __align__(16) __half g_F  [(size_t)TOK * 4 * DIM];
__device__ __align__(16) __half g_Wh [1769472];          // fp16 weights

#define WOFF_QKV  0
#define WOFF_PROJ (3 * DIM * DIM)
#define WOFF_FC1  (WOFF_PROJ + DIM * DIM)
#define WOFF_FC2  (WOFF_FC1 + 4 * DIM * DIM)

// ---------------------------------------------------------------------------
// helpers
// ---------------------------------------------------------------------------
__device__ __forceinline__ float tf32_rna(float x) {
    uint32_t u;
    asm("cvt.rna.tf32.f32 %0, %1;" : "=r"(u) : "f"(x));
    return __uint_as_float(u);
}
__device__ __forceinline__ uint32_t smem_u32(const void* p) {
    uint32_t a;
    asm("{ .reg .u64 t; cvta.to.shared.u64 t, %1; cvt.u32.u64 %0, t; }" : "=r"(a) : "l"(p));
    return a;
}
__device__ __forceinline__ void cp16(uint32_t dst, const void* src) {
    asm volatile("cp.async.cg.shared.global [%0], [%1], 16;" :: "r"(dst), "l"(src));
}
#define CP_COMMIT() asm volatile("cp.async.commit_group;" ::: "memory")
#define CP_WAIT2()  asm volatile("cp.async.wait_group 2;" ::: "memory")

__device__ __forceinline__ void ldsm_x4(uint32_t* r, uint32_t a) {
    asm volatile("ldmatrix.sync.aligned.m8n8.x4.shared.b16 {%0,%1,%2,%3}, [%4];"
                 : "=r"(r[0]), "=r"(r[1]), "=r"(r[2]), "=r"(r[3]) : "r"(a));
}
__device__ __forceinline__ void mma_f16(float* d, const uint32_t* a, const uint32_t* b) {
    asm volatile(
        "mma.sync.aligned.m16n8k16.row.col.f32.f16.f16.f32 "
        "{%0,%1,%2,%3}, {%4,%5,%6,%7}, {%8,%9}, {%0,%1,%2,%3};"
        : "+f"(d[0]), "+f"(d[1]), "+f"(d[2]), "+f"(d[3])
        : "r"(a[0]), "r"(a[1]), "r"(a[2]), "r"(a[3]), "r"(b[0]), "r"(b[1]));
}
__device__ __forceinline__ void mma_tf32(float* d, const float* a, const float* b) {
    uint32_t const* A = reinterpret_cast<uint32_t const*>(a);
    uint32_t const* B = reinterpret_cast<uint32_t const*>(b);
    asm volatile(
        "mma.sync.aligned.m16n8k8.row.col.f32.tf32.tf32.f32 "
        "{%0,%1,%2,%3}, {%4,%5,%6,%7}, {%8,%9}, {%0,%1,%2,%3};"
        : "+f"(d[0]), "+f"(d[1]), "+f"(d[2]), "+f"(d[3])
        : "r"(A[0]), "r"(A[1]), "r"(A[2]), "r"(A[3]), "r"(B[0]), "r"(B[1]));
}

// ---------------------------------------------------------------------------
// 0) weight conversion fp32 -> fp16
// ---------------------------------------------------------------------------
__global__ void cvtw_kernel(const float* __restrict__ src, __half* __restrict__ dst, int n)
{
    int i = blockIdx.x * blockDim.x + threadIdx.x;
    if (i < n) dst[i] = __float2half_rn(src[i]);
}

// ---------------------------------------------------------------------------
// 1) depthwise 3x3 conv PE + residual -> windowed (wi,n,c)
// ---------------------------------------------------------------------------
__global__ void conv_pe_kernel(const float* __restrict__ x,
                               const float* __restrict__ cw,
                               const float* __restrict__ cb,
                               float* __restrict__ X0)
{
    const int cg = blockIdx.x * 8;
    const int h  = blockIdx.y;
    const int b  = blockIdx.z;

    __shared__ float sm[8][3][58];

    const int tid = threadIdx.y * 8 + threadIdx.x;
    const int lc  = tid / 56;
    const int lw  = tid % 56;

    const float* xp = x + ((size_t)(b * DIM + cg + lc) * HH) * WW;
#pragma unroll
    for (int r = 0; r < 3; r++) {
        int hh = h - 1 + r;
        float v = (hh >= 0 && hh < HH) ? xp[hh * WW + lw] : 0.0f;
        sm[lc][r][lw + 1] = v;
        if (lw == 0)  sm[lc][r][0]  = 0.0f;
        if (lw == 55) sm[lc][r][57] = 0.0f;
    }
    __syncthreads();

    const int c = threadIdx.x;
    const int w = threadIdx.y;

    float wreg[9];
    const float* cwp = cw + (size_t)(cg + c) * 9;
#pragma unroll
    for (int i = 0; i < 9; i++) wreg[i] = cwp[i];

    float pe = 0.0f;
#pragma unroll
    for (int kh = 0; kh < 3; kh++)
#pragma unroll
        for (int kw = 0; kw < 3; kw++)
            pe += wreg[kh * 3 + kw] * sm[c][kh][w + kw];

    float val = sm[c][1][w + 1] + pe + cb[cg + c];

    const int wi = (b * 4 + h / WS) * 4 + (w / WS);
    const int n  = (h % WS) * WS + (w % WS);
    X0[((size_t)wi * NTOK + n) * DIM + cg + c] = val;
}

// ---------------------------------------------------------------------------
// 2) LayerNorm; fp16 output (GEMM A operand)
// ---------------------------------------------------------------------------
__global__ void ln_kernel(const float* __restrict__ X,
                          const float* __restrict__ gamma,
                          const float* __restrict__ beta,
                          __half* __restrict__ Y)
{
    const int warp = (blockIdx.x * blockDim.x + threadIdx.x) >> 5;
    const int lane = threadIdx.x & 31;
    if (warp >= TOK) return;

    const float* xp = X + (size_t)warp * DIM;
    float v[12];
    float s = 0.0f;
#pragma unroll
    for (int k = 0; k < 12; k++) { v[k] = xp[lane + 32 * k]; s += v[k]; }
#pragma unroll
    for (int o = 16; o; o >>= 1) s += __shfl_xor_sync(0xffffffffu, s, o);
    const float mean = s * (1.0f / DIM);

    float q = 0.0f;
#pragma unroll
    for (int k = 0; k < 12; k++) { float d = v[k] - mean; q += d * d; }
#pragma unroll
    for (int o = 16; o; o >>= 1) q += __shfl_xor_sync(0xffffffffu, q, o);
    const float inv = rsqrtf(q * (1.0f / DIM) + 1e-5f);

    __half* yp = Y + (size_t)warp * DIM;
#pragma unroll
    for (int k = 0; k < 12; k++) {
        int c = lane + 32 * k;
        yp[c] = __float2half_rn((v[k] - mean) * inv * gamma[c] + beta[c]);
    }
}

// ---------------------------------------------------------------------------
// 3) FP16 mma.sync GEMM: C[M,N] = act(A[M,K] @ W[N,K]^T + bias) (+ R)
//    CTA 128x128, BK=32, 8 warps (2m x 4n), warp 64x32.
//    4-stage cp.async (64KB) -> 2 CTAs/SM. ldmatrix.x4, swizzled.
// ---------------------------------------------------------------------------
#define BM 128
#define BN 128
#define BK 32
#define A_BYTES 8192                         // 128 rows x 64B
#define STAGE_B 16384                        // A 8K + B 8K
#define NSTAGE  4
#define GEMM_SMEM (NSTAGE * STAGE_B)         // 65536

__global__ __launch_bounds__(256, 2)
void hgemm_kernel(const __half* __restrict__ A,
                  const __half* __restrict__ W,
                  const float* __restrict__ bias,
                  const float* __restrict__ R,
                  float* __restrict__ Cf,
                  __half* __restrict__ Ch,
                  int M, int N, int K, int act)
{
    extern __shared__ char smc[];
    const uint32_t smem_base = smem_u32(smc);
    const int tid  = threadIdx.x;
    const int lane = tid & 31;
    const int wid  = tid >> 5;
    const int bm = blockIdx.y * BM;
    const int bn = blockIdx.x * BN;

    const int warp_m = (wid & 1) * 64;
    const int warp_n = (wid >> 1) * 32;

    float acc[4][4][4];
#pragma unroll
    for (int im = 0; im < 4; im++)
#pragma unroll
        for (int in = 0; in < 4; in++)
#pragma unroll
            for (int j = 0; j < 4; j++) acc[im][in][j] = 0.0f;

    // ldmatrix lane geometry
    const int g  = lane >> 3;
    const int r8 = lane & 7;
    const int a_row = warp_m + (g & 1) * 8 + r8;     // + im*16
    const int a_sw  = (a_row >> 1) & 3;
    const int a_cg  = g >> 1;
    const int b_row = warp_n + (g >> 1) * 8 + r8;    // + inp*16
    const int b_sw  = (b_row >> 1) & 3;
    const int b_cg  = g & 1;

    const int NC = K >> 5;

    // fill: thread t -> row t>>1 (A and B), chunk pair (t&1)*2
    const int fr  = tid >> 1;
    const int fc0 = (tid & 1) * 2;
    const int fsw = (fr >> 1) & 3;
    auto fill = [&](int kc, int st) {
        const int k0 = kc << 5;
        const uint32_t sb = smem_base + (uint32_t)st * STAGE_B;
        const __half* Ag = A + (size_t)(bm + fr) * K + k0;
        const __half* Wg = W + (size_t)(bn + fr) * K + k0;
#pragma unroll
        for (int c = 0; c < 2; c++) {
            const int cc = fc0 + c;
            const uint32_t so = (uint32_t)(fr * 64 + ((cc ^ fsw) * 16));
            cp16(sb + so, Ag + cc * 8);
            cp16(sb + A_BYTES + so, Wg + cc * 8);
        }
    };

    fill(0, 0); CP_COMMIT();
    fill(1, 1); CP_COMMIT();
    fill(2, 2); CP_COMMIT();

    for (int kc = 0; kc < NC; kc++) {
        CP_WAIT2();
        __syncthreads();

        if (kc + 3 < NC) fill(kc + 3, (kc + 3) & 3);
        CP_COMMIT();                      // unconditional: constant depth

        const uint32_t ab = smem_base + (uint32_t)(kc & 3) * STAGE_B;
        const uint32_t bb = ab + A_BYTES;

#pragma unroll
        for (int s = 0; s < 2; s++) {
            uint32_t af[4][4], bf[2][4];
#pragma unroll
            for (int im = 0; im < 4; im++)
                ldsm_x4(af[im], ab + (uint32_t)(a_row * 64 + im * 1024 +
                                                (((s * 2 + a_cg) ^ a_sw) * 16)));
#pragma unroll
            for (int inp = 0; inp < 2; inp++)
                ldsm_x4(bf[inp], bb + (uint32_t)(b_row * 64 + inp * 1024 +
                                                 (((s * 2 + b_cg) ^ b_sw) * 16)));
#pragma unroll
            for (int im = 0; im < 4; im++)
#pragma unroll
                for (int in = 0; in < 4; in++)
                    mma_f16(acc[im][in], af[im], &bf[in >> 1][(in & 1) * 2]);
        }
    }

    // epilogue
    const int rq = lane >> 2;
    const int cq = (lane & 3) * 2;
#pragma unroll
    for (int im = 0; im < 4; im++) {
        const int row0 = bm + warp_m + im * 16 + rq;
#pragma unroll
        for (int in = 0; in < 4; in++) {
            const int col = bn + warp_n + in * 8 + cq;
            const float2 bv = *(const float2*)(bias + col);
            float v0 = acc[im][in][0] + bv.x;
            float v1 = acc[im][in][1] + bv.y;
            float v2 = acc[im][in][2] + bv.x;
            float v3 = acc[im][in][3] + bv.y;
            if (act == 1) {
                v0 = 0.5f * v0 * (1.0f + erff(v0 * 0.70710678118654752f));
                v1 = 0.5f * v1 * (1.0f + erff(v1 * 0.70710678118654752f));
                v2 = 0.5f * v2 * (1.0f + erff(v2 * 0.70710678118654752f));
                v3 = 0.5f * v3 * (1.0f + erff(v3 * 0.70710678118654752f));
            }
            if (Ch) {
                *(__half2*)(Ch + (size_t)row0 * N + col) =
                    __halves2half2(__float2half_rn(v0), __float2half_rn(v1));
                *(__half2*)(Ch + (size_t)(row0 + 8) * N + col) =
                    __halves2half2(__float2half_rn(v2), __float2half_rn(v3));
            } else {
                if (R) {
                    const float2 r0 = *(const float2*)(R + (size_t)row0 * N + col);
                    const float2 r1 = *(const float2*)(R + (size_t)(row0 + 8) * N + col);
                    v0 += r0.x; v1 += r0.y; v2 += r1.x; v3 += r1.y;
                }
                *(float2*)(Cf + (size_t)row0 * N + col)       = make_float2(v0, v1);
                *(float2*)(Cf + (size_t)(row0 + 8) * N + col) = make_float2(v2, v3);
            }
        }
    }
}

// ---------------------------------------------------------------------------
// 4) Window attention via mma.sync tf32; QKV input fp16; ATT output fp16.
// ---------------------------------------------------------------------------
#define QK_STR 36
#define V_STR  40
#define P_STR  204
#define MROWS  208
#define ATTN_SMEM ((2 * MROWS * QK_STR + MROWS * V_STR + 8 * 16 * P_STR) * 4)

__global__ __launch_bounds__(256, 1)
void attn_mma_kernel(const __half* __restrict__ QKV, __half* __restrict__ ATT)
{
    const int wi  = blockIdx.x / NH;
    const int hdi = blockIdx.x % NH;

    extern __shared__ float sh[];
    float* qs = sh;
    float* ks = qs + MROWS * QK_STR;
    float* vs = ks + MROWS * QK_STR;
    float* ps = vs + MROWS * V_STR;

    const int tid  = threadIdx.x;
    const int warp = tid >> 5;
    const int lane = tid & 31;
    const int rq = lane >> 2;
    const int kq = lane & 3;
    const float scale = 0.1767766952966369f;

    const __half* base = QKV + (size_t)wi * NTOK * (3 * DIM) + hdi * HD;
    for (int idx = tid; idx < MROWS * 8; idx += 256) {
        const int n = idx >> 3, f4 = idx & 7;
        float4 q = make_float4(0.f, 0.f, 0.f, 0.f), k = q, v = q;
        if (n < NTOK) {
            const __half* src = base + (size_t)n * (3 * DIM) + f4 * 4;
            const __half2 q01 = *(const __half2*)(src);
            const __half2 q23 = *(const __half2*)(src + 2);
            const __half2 k01 = *(const __half2*)(src + DIM);
            const __half2 k23 = *(const __half2*)(src + DIM + 2);
            const __half2 v01 = *(const __half2*)(src + 2 * DIM);
            const __half2 v23 = *(const __half2*)(src + 2 * DIM + 2);
            float2 f;
            f = __half22float2(q01); q.x = tf32_rna(f.x * scale); q.y = tf32_rna(f.y * scale);
            f = __half22float2(q23); q.z = tf32_rna(f.x * scale); q.w = tf32_rna(f.y * scale);
            f = __half22float2(k01); k.x = f.x; k.y = f.y;
            f = __half22float2(k23); k.z = f.x; k.w = f.y;
            f = __half22float2(v01); v.x = f.x; v.y = f.y;
            f = __half22float2(v23); v.z = f.x; v.w = f.y;
        }
        *(float4*)(qs + n * QK_STR + f4 * 4) = q;
        *(float4*)(ks + n * QK_STR + f4 * 4) = k;
        *(float4*)(vs + n * V_STR  + f4 * 4) = v;
    }
    __syncthreads();

    float* pw = ps + warp * 16 * P_STR;
    const int cq2 = kq * 2;

    for (int t = warp; t < 13; t += 8) {
        const int m0 = t * 16;

        float a[4][4];
#pragma unroll
        for (int s = 0; s < 4; s++) {
            const float* qp = qs + (m0 + rq) * QK_STR + s * 8 + kq;
            a[s][0] = qp[0];
            a[s][1] = qp[8 * QK_STR];
            a[s][2] = qp[4];
            a[s][3] = qp[8 * QK_STR + 4];
        }

        float c[25][4];
#pragma unroll
        for (int nt = 0; nt < 25; nt++) { c[nt][0] = c[nt][1] = c[nt][2] = c[nt][3] = 0.f; }
#pragma unroll
        for (int nt = 0; nt < 25; nt++) {
#pragma unroll
            for (int s = 0; s < 4; s++) {
                float b[2];
                const float* kp = ks + (nt * 8 + rq) * QK_STR + s * 8 + kq;
                b[0] = kp[0];
                b[1] = kp[4];
                mma_tf32(c[nt], a[s], b);
            }
        }

        float mx0 = -1e30f, mx1 = -1e30f;
#pragma unroll
        for (int nt = 0; nt < 25; nt++) {
            const int col = nt * 8 + cq2;
            if (col < NTOK)     { mx0 = fmaxf(mx0, c[nt][0]); mx1 = fmaxf(mx1, c[nt][2]); }
            if (col + 1 < NTOK) { mx0 = fmaxf(mx0, c[nt][1]); mx1 = fmaxf(mx1, c[nt][3]); }
        }
        mx0 = fmaxf(mx0, __shfl_xor_sync(0xffffffffu, mx0, 1));
        mx0 = fmaxf(mx0, __shfl_xor_sync(0xffffffffu, mx0, 2));
        mx1 = fmaxf(mx1, __shfl_xor_sync(0xffffffffu, mx1, 1));
        mx1 = fmaxf(mx1, __shfl_xor_sync(0xffffffffu, mx1, 2));

        float sum0 = 0.f, sum1 = 0.f;
#pragma unroll
        for (int nt = 0; nt < 25; nt++) {
            const int col = nt * 8 + cq2;
            float p0 = (col < NTOK)     ? __expf(c[nt][0] - mx0) : 0.f;
            float p1 = (col + 1 < NTOK) ? __expf(c[nt][1] - mx0) : 0.f;
            float p2 = (col < NTOK)     ? __expf(c[nt][2] - mx1) : 0.f;
            float p3 = (col + 1 < NTOK) ? __expf(c[nt][3] - mx1) : 0.f;
            sum0 += p0 + p1;
            sum1 += p2 + p3;
            c[nt][0] = tf32_rna(p0); c[nt][1] = tf32_rna(p1);
            c[nt][2] = tf32_rna(p2); c[nt][3] = tf32_rna(p3);
        }
        sum0 += __shfl_xor_sync(0xffffffffu, sum0, 1);
        sum0 += __shfl_xor_sync(0xffffffffu, sum0, 2);
        sum1 += __shfl_xor_sync(0xffffffffu, sum1, 1);
        sum1 += __shfl_xor_sync(0xffffffffu, sum1, 2);

#pragma unroll
        for (int nt = 0; nt < 25; nt++) {
            *(float2*)(pw + rq * P_STR + nt * 8 + cq2)       = make_float2(c[nt][0], c[nt][1]);
            *(float2*)(pw + (rq + 8) * P_STR + nt * 8 + cq2) = make_float2(c[nt][2], c[nt][3]);
        }
        __syncwarp();

        float o[4][4];
#pragma unroll
        for (int n = 0; n < 4; n++) { o[n][0] = o[n][1] = o[n][2] = o[n][3] = 0.f; }
#pragma unroll
        for (int kt = 0; kt < 25; kt++) {
            float a2[4];
            const float* pp = pw + rq * P_STR + kt * 8 + kq;
            a2[0] = pp[0];
            a2[1] = pp[8 * P_STR];
            a2[2] = pp[4];
            a2[3] = pp[8 * P_STR + 4];
#pragma unroll
            for (int n = 0; n < 4; n++) {
                float b[2];
                const float* vp = vs + (kt * 8 + kq) * V_STR + n * 8 + rq;
                b[0] = vp[0];
                b[1] = vp[4 * V_STR];
                mma_tf32(o[n], a2, b);
            }
        }
        __syncwarp();

        const float inv0 = 1.0f / sum0;
        const float inv1 = 1.0f / sum1;
        const int r0 = m0 + rq, r1 = m0 + rq + 8;
#pragma unroll
        for (int n = 0; n < 4; n++) {
            const int col = hdi * HD + n * 8 + cq2;
            if (r0 < NTOK)
                *(__half2*)(ATT + ((size_t)wi * NTOK + r0) * DIM + col) =
                    __halves2half2(__float2half_rn(o[n][0] * inv0), __float2half_rn(o[n][1] * inv0));
            if (r1 < NTOK)
                *(__half2*)(ATT + ((size_t)wi * NTOK + r1) * DIM + col) =
                    __halves2half2(__float2half_rn(o[n][2] * inv1), __float2half_rn(o[n][3] * inv1));
        }
    }
}

// ---------------------------------------------------------------------------
// 5) Windowed (wi,n,c) -> BCHW output
// ---------------------------------------------------------------------------
__global__ void unwin_kernel(const float* __restrict__ X,
                             float* __restrict__ out)
{
    const int ct = blockIdx.x >> 1, wt = blockIdx.x & 1;
    const int h = blockIdx.y, b = blockIdx.z;
    const int c0 = ct * 32, w0 = wt * 32;

    __shared__ float sm[32][33];
    const int tx = threadIdx.x, ty = threadIdx.y;

#pragma unroll
    for (int k = 0; k < 4; k++) {
        int r = ty + 8 * k;
        int w = w0 + r;
        if (w < WW) {
            int wi = (b * 4 + h / WS) * 4 + w / WS;
            int n  = (h % WS) * WS + (w % WS);
            sm[r][tx] = X[((size_t)wi * NTOK + n) * DIM + c0 + tx];
        }
    }
    __syncthreads();

#pragma unroll
    for (int k = 0; k < 4; k++) {
        int c = c0 + ty + 8 * k;
        int w = w0 + tx;
        if (w < WW)
            out[(((size_t)b * DIM + c) * HH + h) * WW + w] = sm[tx][ty + 8 * k];
    }
}

// ---------------------------------------------------------------------------
// Launch
// ---------------------------------------------------------------------------
extern "C" void kernel_launch(void* const* d_in, const int* in_sizes, int n_in,
                              void* d_out, int out_size)
{
    const float* x      = (const float*)d_in[0];
    const float* conv_w = (const float*)d_in[1];
    const float* conv_b = (const float*)d_in[2];
    const float* ln1_g  = (const float*)d_in[3];
    const float* ln1_b  = (const float*)d_in[4];
    const float* qkv_w  = (const float*)d_in[5];
    const float* qkv_b  = (const float*)d_in[6];
    const float* proj_w = (const float*)d_in[7];
    const float* proj_b = (const float*)d_in[8];
    const float* ln2_g  = (const float*)d_in[9];
    const float* ln2_b  = (const float*)d_in[10];
    const float* fc1_w  = (const float*)d_in[11];
    const float* fc1_b  = (const float*)d_in[12];
    const float* fc2_w  = (const float*)d_in[13];
    const float* fc2_b  = (const float*)d_in[14];
    float* out = (float*)d_out;

    float *X0, *X1;
    __half *Y, *QKV, *ATT, *F, *Wh;
    cudaGetSymbolAddress((void**)&X0,  g_X0);
    cudaGetSymbolAddress((void**)&Y,   g_Y);
    cudaGetSymbolAddress((void**)&QKV, g_QKV);
    cudaGetSymbolAddress((void**)&ATT, g_ATT);
    cudaGetSymbolAddress((void**)&X1,  g_X1);
    cudaGetSymbolAddress((void**)&F,   g_F);
    cudaGetSymbolAddress((void**)&Wh,  g_Wh);

    cudaFuncSetAttribute(attn_mma_kernel, cudaFuncAttributeMaxDynamicSharedMemorySize, ATTN_SMEM);
    cudaFuncSetAttribute(hgemm_kernel, cudaFuncAttributeMaxDynamicSharedMemorySize, GEMM_SMEM);

    // 0) fp16 weights
    cvtw_kernel<<<(3 * DIM * DIM + 255) / 256, 256>>>(qkv_w,  Wh + WOFF_QKV,  3 * DIM * DIM);
    cvtw_kernel<<<(DIM * DIM + 255) / 256, 256>>>(proj_w, Wh + WOFF_PROJ, DIM * DIM);
    cvtw_kernel<<<(4 * DIM * DIM + 255) / 256, 256>>>(fc1_w,  Wh + WOFF_FC1,  4 * DIM * DIM);
    cvtw_kernel<<<(4 * DIM * DIM + 255) / 256, 256>>>(fc2_w,  Wh + WOFF_FC2,  4 * DIM * DIM);

    // 1) conv PE + residual -> X0
    conv_pe_kernel<<<dim3(DIM / 8, HH, BATCH), dim3(8, 56)>>>(x, conv_w, conv_b, X0);

    // 2) LN1 -> Y (fp16)
    ln_kernel<<<TOK / 8, 256>>>(X0, ln1_g, ln1_b, Y);

    // 3) QKV GEMM (fp16 in, fp16 out)
    hgemm_kernel<<<dim3(3 * DIM / BN, TOK / BM), 256, GEMM_SMEM>>>(
        Y, Wh + WOFF_QKV, qkv_b, nullptr, nullptr, QKV, TOK, 3 * DIM, DIM, 0);

    // 4) window attention -> ATT (fp16)
    attn_mma_kernel<<<NWIN * NH, 256, ATTN_SMEM>>>(QKV, ATT);

    // 5) proj GEMM + residual(X0) -> X1 (fp32)
    hgemm_kernel<<<dim3(DIM / BN, TOK / BM), 256, GEMM_SMEM>>>(
        ATT, Wh + WOFF_PROJ, proj_b, X0, X1, nullptr, TOK, DIM, DIM, 0);

    // 6) LN2 -> Y (fp16)
    ln_kernel<<<TOK / 8, 256>>>(X1, ln2_g, ln2_b, Y);

    // 7) FC1 GEMM + GELU -> F (fp16)
    hgemm_kernel<<<dim3(4 * DIM / BN, TOK / BM), 256, GEMM_SMEM>>>(
        Y, Wh + WOFF_FC1, fc1_b, nullptr, nullptr, F, TOK, 4 * DIM, DIM, 1);

    // 8) FC2 GEMM + residual(X1) -> X0 (fp32)
    hgemm_kernel<<<dim3(DIM / BN, TOK / BM), 256, GEMM_SMEM>>>(
        F, Wh + WOFF_FC2, fc2_b, X1, X0, nullptr, TOK, DIM, 4 * DIM, 0);

    // 9) un-window -> BCHW
    unwin_kernel<<<dim3(24, HH, BATCH), dim3(32, 8)>>>(X0, out);
}

// round 7
// speedup vs baseline: 4.6334x; 1.0152x over previous
#include <cuda_runtime.h>
#include <cuda_bf16.h>
#include <cuda_fp16.h>
#include <math.h>
#include <cstdint>

// ---------------------------------------------------------------------------
// Problem constants
// ---------------------------------------------------------------------------
#define DIM   384
#define NH    12
#define HD    32
#define WS    14
#define BATCH 16
#define HH    56
#define WW    56
#define NWIN  256
#define NTOK  196
#define TOK   50176          // NWIN*NTOK

// ---------------------------------------------------------------------------
// Scratch
// ---------------------------------------------------------------------------
__device__ __align__(16) float  g_X0 [(size_t)TOK * DIM];
__device__ __align__(16) __half g_Y  [(size_t)TOK * DIM];
__device__ __align__(16) __half g_QKV[(size_t)TOK * 3 * DIM];
__device__ __align__(16) __half g_ATT[(size_t)TOK * DIM];
__device__ __align__(16) float  g_X1 [(size_t)TOK * DIM];
__device__ __align__(16) __half g_F  [(size_t)TOK * 4 * DIM];
__device__ __align__(16) __half g_Wh [1769472];          // fp16 weights

#define WOFF_QKV  0
#define WOFF_PROJ (3 * DIM * DIM)
#define WOFF_FC1  (WOFF_PROJ + DIM * DIM)
#define WOFF_FC2  (WOFF_FC1 + 4 * DIM * DIM)

// ---------------------------------------------------------------------------
// helpers
// ---------------------------------------------------------------------------
__device__ __forceinline__ uint32_t smem_u32(const void* p) {
    uint32_t a;
    asm("{ .reg .u64 t; cvta.to.shared.u64 t, %1; cvt.u32.u64 %0, t; }" : "=r"(a) : "l"(p));
    return a;
}
__device__ __forceinline__ void cp16(uint32_t dst, const void* src) {
    asm volatile("cp.async.cg.shared.global [%0], [%1], 16;" :: "r"(dst), "l"(src));
}
#define CP_COMMIT() asm volatile("cp.async.commit_group;" ::: "memory")
#define CP_WAIT1()  asm volatile("cp.async.wait_group 1;" ::: "memory")

__device__ __forceinline__ void ldsm_x4(uint32_t* r, uint32_t a) {
    asm volatile("ldmatrix.sync.aligned.m8n8.x4.shared.b16 {%0,%1,%2,%3}, [%4];"
                 : "=r"(r[0]), "=r"(r[1]), "=r"(r[2]), "=r"(r[3]) : "r"(a));
}
__device__ __forceinline__ void ldsm_x4_t(uint32_t* r, uint32_t a) {
    asm volatile("ldmatrix.sync.aligned.m8n8.x4.trans.shared.b16 {%0,%1,%2,%3}, [%4];"
                 : "=r"(r[0]), "=r"(r[1]), "=r"(r[2]), "=r"(r[3]) : "r"(a));
}
__device__ __forceinline__ void mma_f16(float* d, const uint32_t* a, const uint32_t* b) {
    asm volatile(
        "mma.sync.aligned.m16n8k16.row.col.f32.f16.f16.f32 "
        "{%0,%1,%2,%3}, {%4,%5,%6,%7}, {%8,%9}, {%0,%1,%2,%3};"
        : "+f"(d[0]), "+f"(d[1]), "+f"(d[2]), "+f"(d[3])
        : "r"(a[0]), "r"(a[1]), "r"(a[2]), "r"(a[3]), "r"(b[0]), "r"(b[1]));
}
__device__ __forceinline__ uint32_t pack_h2(float x, float y) {
    __half2 h = __floats2half2_rn(x, y);
    return *reinterpret_cast<uint32_t*>(&h);
}

// ---------------------------------------------------------------------------
// 0) weight conversion fp32 -> fp16
// ---------------------------------------------------------------------------
__global__ void cvtw_kernel(const float* __restrict__ src, __half* __restrict__ dst, int n)
{
    int i = blockIdx.x * blockDim.x + threadIdx.x;
    if (i < n) dst[i] = __float2half_rn(src[i]);
}

// ---------------------------------------------------------------------------
// 1) depthwise 3x3 conv PE + residual -> windowed (wi,n,c)
// ---------------------------------------------------------------------------
__global__ void conv_pe_kernel(const float* __restrict__ x,
                               const float* __restrict__ cw,
                               const float* __restrict__ cb,
                               float* __restrict__ X0)
{
    const int cg = blockIdx.x * 8;
    const int h  = blockIdx.y;
    const int b  = blockIdx.z;

    __shared__ float sm[8][3][58];

    const int tid = threadIdx.y * 8 + threadIdx.x;
    const int lc  = tid / 56;
    const int lw  = tid % 56;

    const float* xp = x + ((size_t)(b * DIM + cg + lc) * HH) * WW;
#pragma unroll
    for (int r = 0; r < 3; r++) {
        int hh = h - 1 + r;
        float v = (hh >= 0 && hh < HH) ? xp[hh * WW + lw] : 0.0f;
        sm[lc][r][lw + 1] = v;
        if (lw == 0)  sm[lc][r][0]  = 0.0f;
        if (lw == 55) sm[lc][r][57] = 0.0f;
    }
    __syncthreads();

    const int c = threadIdx.x;
    const int w = threadIdx.y;

    float wreg[9];
    const float* cwp = cw + (size_t)(cg + c) * 9;
#pragma unroll
    for (int i = 0; i < 9; i++) wreg[i] = cwp[i];

    float pe = 0.0f;
#pragma unroll
    for (int kh = 0; kh < 3; kh++)
#pragma unroll
        for (int kw = 0; kw < 3; kw++)
            pe += wreg[kh * 3 + kw] * sm[c][kh][w + kw];

    float val = sm[c][1][w + 1] + pe + cb[cg + c];

    const int wi = (b * 4 + h / WS) * 4 + (w / WS);
    const int n  = (h % WS) * WS + (w % WS);
    X0[((size_t)wi * NTOK + n) * DIM + cg + c] = val;
}

// ---------------------------------------------------------------------------
// 2) LayerNorm; fp16 output (GEMM A operand)
// ---------------------------------------------------------------------------
__global__ void ln_kernel(const float* __restrict__ X,
                          const float* __restrict__ gamma,
                          const float* __restrict__ beta,
                          __half* __restrict__ Y)
{
    const int warp = (blockIdx.x * blockDim.x + threadIdx.x) >> 5;
    const int lane = threadIdx.x & 31;
    if (warp >= TOK) return;

    const float* xp = X + (size_t)warp * DIM;
    float v[12];
    float s = 0.0f;
#pragma unroll
    for (int k = 0; k < 12; k++) { v[k] = xp[lane + 32 * k]; s += v[k]; }
#pragma unroll
    for (int o = 16; o; o >>= 1) s += __shfl_xor_sync(0xffffffffu, s, o);
    const float mean = s * (1.0f / DIM);

    float q = 0.0f;
#pragma unroll
    for (int k = 0; k < 12; k++) { float d = v[k] - mean; q += d * d; }
#pragma unroll
    for (int o = 16; o; o >>= 1) q += __shfl_xor_sync(0xffffffffu, q, o);
    const float inv = rsqrtf(q * (1.0f / DIM) + 1e-5f);

    __half* yp = Y + (size_t)warp * DIM;
#pragma unroll
    for (int k = 0; k < 12; k++) {
        int c = lane + 32 * k;
        yp[c] = __float2half_rn((v[k] - mean) * inv * gamma[c] + beta[c]);
    }
}

// ---------------------------------------------------------------------------
// 3) FP16 mma.sync GEMM: C[M,N] = act(A[M,K] @ W[N,K]^T + bias) (+ R)
//    CTA 128x128, BK=64, 8 warps (2m x 4n), warp 64x32.
//    3-stage cp.async (108KB) -> 2 CTAs/SM. ldmatrix.x4, 144B odd-stride rows.
// ---------------------------------------------------------------------------
#define BM 128
#define BN 128
#define BK 64
#define ROW_B 144                            // bytes per smem row (9 granules, odd)
#define A_BYTES (128 * ROW_B)                // 18432
#define STAGE_B (2 * A_BYTES)                // 36864
#define NSTAGE  3
#define GEMM_SMEM (NSTAGE * STAGE_B)         // 110592

__global__ __launch_bounds__(256, 2)
void hgemm_kernel(const __half* __restrict__ A,
                  const __half* __restrict__ W,
                  const float* __restrict__ bias,
                  const float* __restrict__ R,
                  float* __restrict__ Cf,
                  __half* __restrict__ Ch,
                  int M, int N, int K, int act)
{
    extern __shared__ char smc[];
    const uint32_t smem_base = smem_u32(smc);
    const int tid  = threadIdx.x;
    const int lane = tid & 31;
    const int wid  = tid >> 5;
    const int bm = blockIdx.y * BM;
    const int bn = blockIdx.x * BN;

    const int warp_m = (wid & 1) * 64;
    const int warp_n = (wid >> 1) * 32;

    float acc[4][4][4];
#pragma unroll
    for (int im = 0; im < 4; im++)
#pragma unroll
        for (int in = 0; in < 4; in++)
#pragma unroll
            for (int j = 0; j < 4; j++) acc[im][in][j] = 0.0f;

    // ldmatrix lane geometry
    const int g  = lane >> 3;
    const int r8 = lane & 7;
    const int a_row = warp_m + (g & 1) * 8 + r8;     // + im*16
    const int a_cg  = g >> 1;                        // 16B chunk within k16
    const int b_row = warp_n + (g >> 1) * 8 + r8;    // + inp*16
    const int b_cg  = g & 1;

    const int NC = K >> 6;

    // fill: thread t -> row t>>1, chunks (t&1)*4 .. +3  (128B of k per row)
    const int fr  = tid >> 1;
    const int fc0 = (tid & 1) * 4;
    auto fill = [&](int kc, int st) {
        const int k0 = kc << 6;
        const uint32_t sb = smem_base + (uint32_t)st * STAGE_B;
        const __half* Ag = A + (size_t)(bm + fr) * K + k0;
        const __half* Wg = W + (size_t)(bn + fr) * K + k0;
#pragma unroll
        for (int c = 0; c < 4; c++) {
            const int cc = fc0 + c;
            const uint32_t so = (uint32_t)(fr * ROW_B + cc * 16);
            cp16(sb + so, Ag + cc * 8);
            cp16(sb + A_BYTES + so, Wg + cc * 8);
        }
    };

    fill(0, 0); CP_COMMIT();
    fill(1, 1); CP_COMMIT();

    for (int kc = 0; kc < NC; kc++) {
        CP_WAIT1();
        __syncthreads();

        if (kc + 2 < NC) fill(kc + 2, (kc + 2) % NSTAGE);
        CP_COMMIT();                      // unconditional: constant depth

        const uint32_t ab = smem_base + (uint32_t)(kc % NSTAGE) * STAGE_B;
        const uint32_t bb = ab + A_BYTES;

#pragma unroll
        for (int s = 0; s < 4; s++) {
            uint32_t af[4][4], bf[2][4];
#pragma unroll
            for (int im = 0; im < 4; im++)
                ldsm_x4(af[im], ab + (uint32_t)((a_row + im * 16) * ROW_B +
                                                (s * 2 + a_cg) * 16));
#pragma unroll
            for (int inp = 0; inp < 2; inp++)
                ldsm_x4(bf[inp], bb + (uint32_t)((b_row + inp * 16) * ROW_B +
                                                 (s * 2 + b_cg) * 16));
#pragma unroll
            for (int im = 0; im < 4; im++)
#pragma unroll
                for (int in = 0; in < 4; in++)
                    mma_f16(acc[im][in], af[im], &bf[in >> 1][(in & 1) * 2]);
        }
    }

    // epilogue
    const int rq = lane >> 2;
    const int cq = (lane & 3) * 2;
#pragma unroll
    for (int im = 0; im < 4; im++) {
        const int row0 = bm + warp_m + im * 16 + rq;
#pragma unroll
        for (int in = 0; in < 4; in++) {
            const int col = bn + warp_n + in * 8 + cq;
            const float2 bv = *(const float2*)(bias + col);
            float v0 = acc[im][in][0] + bv.x;
            float v1 = acc[im][in][1] + bv.y;
            float v2 = acc[im][in][2] + bv.x;
            float v3 = acc[im][in][3] + bv.y;
            if (act == 1) {
                v0 = 0.5f * v0 * (1.0f + erff(v0 * 0.70710678118654752f));
                v1 = 0.5f * v1 * (1.0f + erff(v1 * 0.70710678118654752f));
                v2 = 0.5f * v2 * (1.0f + erff(v2 * 0.70710678118654752f));
                v3 = 0.5f * v3 * (1.0f + erff(v3 * 0.70710678118654752f));
            }
            if (Ch) {
                *(__half2*)(Ch + (size_t)row0 * N + col) =
                    __halves2half2(__float2half_rn(v0), __float2half_rn(v1));
                *(__half2*)(Ch + (size_t)(row0 + 8) * N + col) =
                    __halves2half2(__float2half_rn(v2), __float2half_rn(v3));
            } else {
                if (R) {
                    const float2 r0 = *(const float2*)(R + (size_t)row0 * N + col);
                    const float2 r1 = *(const float2*)(R + (size_t)(row0 + 8) * N + col);
                    v0 += r0.x; v1 += r0.y; v2 += r1.x; v3 += r1.y;
                }
                *(float2*)(Cf + (size_t)row0 * N + col)       = make_float2(v0, v1);
                *(float2*)(Cf + (size_t)(row0 + 8) * N + col) = make_float2(v2, v3);
            }
        }
    }
}

// ---------------------------------------------------------------------------
// 4) Window attention, full fp16 mma. 128 threads (4 warps), occupancy 2.
//    S accumulators repack DIRECTLY into PV A-fragments (no P smem).
//    Q/K/V smem rows: 40 halfs (80B = 5 granules, odd -> conflict-free ldsm).
// ---------------------------------------------------------------------------
#define AQ_STR 40
#define AROWS  208
#define ATTN_SMEM (3 * AROWS * AQ_STR * 2)      // 49920 B

__global__ __launch_bounds__(128, 2)
void attn_h_kernel(const __half* __restrict__ QKV, __half* __restrict__ ATT)
{
    const int wi  = blockIdx.x / NH;
    const int hdi = blockIdx.x % NH;

    extern __shared__ __half shh[];
    __half* qs = shh;
    __half* ks = qs + AROWS * AQ_STR;
    __half* vs = ks + AROWS * AQ_STR;

    const int tid  = threadIdx.x;
    const int warp = tid >> 5;
    const int lane = tid & 31;
    const float scale = 0.1767766952966369f;   // 1/sqrt(32)

    // ---- load Q/K/V rows (16B chunks); rows >= 196 zeroed ----
    const __half* base = QKV + (size_t)wi * NTOK * (3 * DIM) + hdi * HD;
    for (int idx = tid; idx < AROWS * 4; idx += 128) {
        const int row = idx >> 2, c = idx & 3;
        uint4 q = make_uint4(0, 0, 0, 0), k = q, v = q;
        if (row < NTOK) {
            const __half* src = base + (size_t)row * (3 * DIM) + c * 8;
            q = *(const uint4*)(src);
            k = *(const uint4*)(src + DIM);
            v = *(const uint4*)(src + 2 * DIM);
        }
        *(uint4*)(qs + row * AQ_STR + c * 8) = q;
        *(uint4*)(ks + row * AQ_STR + c * 8) = k;
        *(uint4*)(vs + row * AQ_STR + c * 8) = v;
    }
    __syncthreads();

    const uint32_t qb = smem_u32(qs);
    const uint32_t kb = smem_u32(ks);
    const uint32_t vb = smem_u32(vs);

    // ldmatrix lane geometry
    const int g  = lane >> 3;
    const int r8 = lane & 7;
    const int a_row_off = (g & 1) * 8 + r8;      // A / V-trans pattern
    const int a_cg      = (g >> 1) * 16;         // byte chunk
    const int b_row_off = (g >> 1) * 8 + r8;     // B (K) pattern
    const int b_cg      = (g & 1) * 16;

    const int rq  = lane >> 2;
    const int cq2 = (lane & 3) * 2;

    for (int t = warp; t < 13; t += 4) {
        const int m0 = t * 16;

        // ---- Q A-fragments: 2 k-steps of 16 ----
        uint32_t af[2][4];
#pragma unroll
        for (int s = 0; s < 2; s++)
            ldsm_x4(af[s], qb + (uint32_t)((m0 + a_row_off) * 80 + a_cg + s * 32));

        // ---- S = Q K^T over 26 n-tiles (13 pairs) ----
        float c[26][4];
#pragma unroll
        for (int nt = 0; nt < 26; nt++) { c[nt][0] = c[nt][1] = c[nt][2] = c[nt][3] = 0.f; }
#pragma unroll
        for (int np = 0; np < 13; np++) {
#pragma unroll
            for (int s = 0; s < 2; s++) {
                uint32_t bf[4];
                ldsm_x4(bf, kb + (uint32_t)((np * 16 + b_row_off) * 80 + b_cg + s * 32));
                mma_f16(c[2 * np],     af[s], &bf[0]);
                mma_f16(c[2 * np + 1], af[s], &bf[2]);
            }
        }

        // ---- masked softmax (scale folded into exp arg) ----
        float mx0 = -1e30f, mx1 = -1e30f;
#pragma unroll
        for (int nt = 0; nt < 26; nt++) {
            const int col = nt * 8 + cq2;
            if (col < NTOK)     { mx0 = fmaxf(mx0, c[nt][0]); mx1 = fmaxf(mx1, c[nt][2]); }
            if (col + 1 < NTOK) { mx0 = fmaxf(mx0, c[nt][1]); mx1 = fmaxf(mx1, c[nt][3]); }
        }
        mx0 = fmaxf(mx0, __shfl_xor_sync(0xffffffffu, mx0, 1));
        mx0 = fmaxf(mx0, __shfl_xor_sync(0xffffffffu, mx0, 2));
        mx1 = fmaxf(mx1, __shfl_xor_sync(0xffffffffu, mx1, 1));
        mx1 = fmaxf(mx1, __shfl_xor_sync(0xffffffffu, mx1, 2));

        uint32_t ph[26][2];
        float sum0 = 0.f, sum1 = 0.f;
#pragma unroll
        for (int nt = 0; nt < 26; nt++) {
            const int col = nt * 8 + cq2;
            float p0 = (col < NTOK)     ? __expf((c[nt][0] - mx0) * scale) : 0.f;
            float p1 = (col + 1 < NTOK) ? __expf((c[nt][1] - mx0) * scale) : 0.f;
            float p2 = (col < NTOK)     ? __expf((c[nt][2] - mx1) * scale) : 0.f;
            float p3 = (col + 1 < NTOK) ? __expf((c[nt][3] - mx1) * scale) : 0.f;
            sum0 += p0 + p1;
            sum1 += p2 + p3;
            ph[nt][0] = pack_h2(p0, p1);        // rows rq    : PV A-frag regs 0/2
            ph[nt][1] = pack_h2(p2, p3);        // rows rq+8  : PV A-frag regs 1/3
        }
        sum0 += __shfl_xor_sync(0xffffffffu, sum0, 1);
        sum0 += __shfl_xor_sync(0xffffffffu, sum0, 2);
        sum1 += __shfl_xor_sync(0xffffffffu, sum1, 1);
        sum1 += __shfl_xor_sync(0xffffffffu, sum1, 2);

        // ---- O = P V : 13 k-steps of 16; A from registers (zero smem) ----
        float o[4][4];
#pragma unroll
        for (int n = 0; n < 4; n++) { o[n][0] = o[n][1] = o[n][2] = o[n][3] = 0.f; }
#pragma unroll
        for (int kt = 0; kt < 13; kt++) {
            uint32_t a[4] = { ph[2 * kt][0], ph[2 * kt][1],
                              ph[2 * kt + 1][0], ph[2 * kt + 1][1] };
            uint32_t v0f[4], v1f[4];
            ldsm_x4_t(v0f, vb + (uint32_t)((kt * 16 + a_row_off) * 80 + a_cg));
            ldsm_x4_t(v1f, vb + (uint32_t)((kt * 16 + a_row_off) * 80 + a_cg + 32));
            mma_f16(o[0], a, &v0f[0]);
            mma_f16(o[1], a, &v0f[2]);
            mma_f16(o[2], a, &v1f[0]);
            mma_f16(o[3], a, &v1f[2]);
        }

        // ---- normalize + store fp16 ----
        const float inv0 = 1.0f / sum0;
        const float inv1 = 1.0f / sum1;
        const int r0 = m0 + rq, r1 = m0 + rq + 8;
#pragma unroll
        for (int n = 0; n < 4; n++) {
            const int col = hdi * HD + n * 8 + cq2;
            if (r0 < NTOK)
                *(__half2*)(ATT + ((size_t)wi * NTOK + r0) * DIM + col) =
                    __halves2half2(__float2half_rn(o[n][0] * inv0), __float2half_rn(o[n][1] * inv0));
            if (r1 < NTOK)
                *(__half2*)(ATT + ((size_t)wi * NTOK + r1) * DIM + col) =
                    __halves2half2(__float2half_rn(o[n][2] * inv1), __float2half_rn(o[n][3] * inv1));
        }
    }
}

// ---------------------------------------------------------------------------
// 5) Windowed (wi,n,c) -> BCHW output
// ---------------------------------------------------------------------------
__global__ void unwin_kernel(const float* __restrict__ X,
                             float* __restrict__ out)
{
    const int ct = blockIdx.x >> 1, wt = blockIdx.x & 1;
    const int h = blockIdx.y, b = blockIdx.z;
    const int c0 = ct * 32, w0 = wt * 32;

    __shared__ float sm[32][33];
    const int tx = threadIdx.x, ty = threadIdx.y;

#pragma unroll
    for (int k = 0; k < 4; k++) {
        int r = ty + 8 * k;
        int w = w0 + r;
        if (w < WW) {
            int wi = (b * 4 + h / WS) * 4 + w / WS;
            int n  = (h % WS) * WS + (w % WS);
            sm[r][tx] = X[((size_t)wi * NTOK + n) * DIM + c0 + tx];
        }
    }
    __syncthreads();

#pragma unroll
    for (int k = 0; k < 4; k++) {
        int c = c0 + ty + 8 * k;
        int w = w0 + tx;
        if (w < WW)
            out[(((size_t)b * DIM + c) * HH + h) * WW + w] = sm[tx][ty + 8 * k];
    }
}

// ---------------------------------------------------------------------------
// Launch
// ---------------------------------------------------------------------------
extern "C" void kernel_launch(void* const* d_in, const int* in_sizes, int n_in,
                              void* d_out, int out_size)
{
    const float* x      = (const float*)d_in[0];
    const float* conv_w = (const float*)d_in[1];
    const float* conv_b = (const float*)d_in[2];
    const float* ln1_g  = (const float*)d_in[3];
    const float* ln1_b  = (const float*)d_in[4];
    const float* qkv_w  = (const float*)d_in[5];
    const float* qkv_b  = (const float*)d_in[6];
    const float* proj_w = (const float*)d_in[7];
    const float* proj_b = (const float*)d_in[8];
    const float* ln2_g  = (const float*)d_in[9];
    const float* ln2_b  = (const float*)d_in[10];
    const float* fc1_w  = (const float*)d_in[11];
    const float* fc1_b  = (const float*)d_in[12];
    const float* fc2_w  = (const float*)d_in[13];
    const float* fc2_b  = (const float*)d_in[14];
    float* out = (float*)d_out;

    float *X0, *X1;
    __half *Y, *QKV, *ATT, *F, *Wh;
    cudaGetSymbolAddress((void**)&X0,  g_X0);
    cudaGetSymbolAddress((void**)&Y,   g_Y);
    cudaGetSymbolAddress((void**)&QKV, g_QKV);
    cudaGetSymbolAddress((void**)&ATT, g_ATT);
    cudaGetSymbolAddress((void**)&X1,  g_X1);
    cudaGetSymbolAddress((void**)&F,   g_F);
    cudaGetSymbolAddress((void**)&Wh,  g_Wh);

    cudaFuncSetAttribute(attn_h_kernel, cudaFuncAttributeMaxDynamicSharedMemorySize, ATTN_SMEM);
    cudaFuncSetAttribute(hgemm_kernel, cudaFuncAttributeMaxDynamicSharedMemorySize, GEMM_SMEM);

    // 0) fp16 weights
    cvtw_kernel<<<(3 * DIM * DIM + 255) / 256, 256>>>(qkv_w,  Wh + WOFF_QKV,  3 * DIM * DIM);
    cvtw_kernel<<<(DIM * DIM + 255) / 256, 256>>>(proj_w, Wh + WOFF_PROJ, DIM * DIM);
    cvtw_kernel<<<(4 * DIM * DIM + 255) / 256, 256>>>(fc1_w,  Wh + WOFF_FC1,  4 * DIM * DIM);
    cvtw_kernel<<<(4 * DIM * DIM + 255) / 256, 256>>>(fc2_w,  Wh + WOFF_FC2,  4 * DIM * DIM);

    // 1) conv PE + residual -> X0
    conv_pe_kernel<<<dim3(DIM / 8, HH, BATCH), dim3(8, 56)>>>(x, conv_w, conv_b, X0);

    // 2) LN1 -> Y (fp16)
    ln_kernel<<<TOK / 8, 256>>>(X0, ln1_g, ln1_b, Y);

    // 3) QKV GEMM (fp16 in, fp16 out)
    hgemm_kernel<<<dim3(3 * DIM / BN, TOK / BM), 256, GEMM_SMEM>>>(
        Y, Wh + WOFF_QKV, qkv_b, nullptr, nullptr, QKV, TOK, 3 * DIM, DIM, 0);

    // 4) window attention -> ATT (fp16)
    attn_h_kernel<<<NWIN * NH, 128, ATTN_SMEM>>>(QKV, ATT);

    // 5) proj GEMM + residual(X0) -> X1 (fp32)
    hgemm_kernel<<<dim3(DIM / BN, TOK / BM), 256, GEMM_SMEM>>>(
        ATT, Wh + WOFF_PROJ, proj_b, X0, X1, nullptr, TOK, DIM, DIM, 0);

    // 6) LN2 -> Y (fp16)
    ln_kernel<<<TOK / 8, 256>>>(X1, ln2_g, ln2_b, Y);

    // 7) FC1 GEMM + GELU -> F (fp16)
    hgemm_kernel<<<dim3(4 * DIM / BN, TOK / BM), 256, GEMM_SMEM>>>(
        Y, Wh + WOFF_FC1, fc1_b, nullptr, nullptr, F, TOK, 4 * DIM, DIM, 1);

    // 8) FC2 GEMM + residual(X1) -> X0 (fp32)
    hgemm_kernel<<<dim3(DIM / BN, TOK / BM), 256, GEMM_SMEM>>>(
        F, Wh + WOFF_FC2, fc2_b, X1, X0, nullptr, TOK, DIM, 4 * DIM, 0);

    // 9) un-window -> BCHW
    unwin_kernel<<<dim3(24, HH, BATCH), dim3(32, 8)>>>(X0, out);
}